// round 3
// baseline (speedup 1.0000x reference)
#include <cuda_runtime.h>
#include <cstdint>

#define DMODEL 512
#define DINNER 1024
#define DSTATE 16
#define DTRANK 32
#define BSZ 8
#define SEQ 2048
#define NTOK (BSZ*SEQ)      /* 16384 tokens */
#define DEPTH 2

// ---------------- scratch (device globals; no allocation allowed) ----------------
__device__ float g_xn[NTOK*DMODEL];                 // layernorm output
__device__ float g_xz[NTOK*2*DINNER];               // in_proj output (xi | z)
__device__ float g_xc[NTOK*DINNER];                 // conv+silu output (u)
__device__ float g_dbc[NTOK*64];                    // x_proj output (dt|B|C)
__device__ float g_delta[NTOK*DINNER];              // softplus(dt@dtw + dtb)
__device__ float g_y[NTOK*DINNER];                  // scan output (gated)
__device__ float g_x1[NTOK*DMODEL];                 // residual stream after layer0
__device__ float g_Aneg[DEPTH*DINNER*DSTATE];       // A = -exp(A_log)
__device__ int   g_flag[DEPTH];                     // 0 => A[e][n]==(n+1)*A[e][0]

// ---------------- small helpers ----------------
__device__ __forceinline__ float softplus_f(float v) {
    return (v > 20.f) ? v : log1pf(expf(v));
}
__device__ __forceinline__ float silu_f(float v) {
    return __fdividef(v, 1.f + __expf(-v));
}

// ---------------- init / precompute ----------------
__global__ void init_k() {
    if (threadIdx.x < DEPTH) g_flag[threadIdx.x] = 0;
}

__global__ void prep_k(const float* __restrict__ Alog) {
    int idx = blockIdx.x * blockDim.x + threadIdx.x;
    if (idx >= DEPTH * DINNER * DSTATE) return;
    float a = -expf(Alog[idx]);
    g_Aneg[idx] = a;
    int n = idx & 15;
    float a0 = -expf(Alog[idx & ~15]);
    if (fabsf(a - (float)(n + 1) * a0) > 1e-4f * fabsf(a) + 1e-12f)
        atomicOr(&g_flag[idx >> 14], 1);   // DINNER*DSTATE = 16384 = 2^14
}

// ---------------- LayerNorm: one warp per token ----------------
__global__ void __launch_bounds__(256)
ln_k(const float* __restrict__ x, const float* __restrict__ w,
     const float* __restrict__ b, float* __restrict__ o)
{
    int token = blockIdx.x * (blockDim.x >> 5) + (threadIdx.x >> 5);
    int lane = threadIdx.x & 31;
    const float4* xr = (const float4*)(x + (size_t)token * DMODEL);
    float4 v[4];
    float s = 0.f, sq = 0.f;
#pragma unroll
    for (int i = 0; i < 4; i++) {
        v[i] = xr[lane + 32 * i];
        s  += v[i].x + v[i].y + v[i].z + v[i].w;
        sq += v[i].x*v[i].x + v[i].y*v[i].y + v[i].z*v[i].z + v[i].w*v[i].w;
    }
#pragma unroll
    for (int off = 16; off; off >>= 1) {
        s  += __shfl_xor_sync(0xffffffffu, s,  off);
        sq += __shfl_xor_sync(0xffffffffu, sq, off);
    }
    float mu  = s * (1.f / DMODEL);
    float var = sq * (1.f / DMODEL) - mu * mu;
    float rs  = rsqrtf(var + 1e-5f);
    const float4* wr = (const float4*)w;
    const float4* br = (const float4*)b;
    float4* orow = (float4*)(o + (size_t)token * DMODEL);
#pragma unroll
    for (int i = 0; i < 4; i++) {
        float4 wv = wr[lane + 32 * i], bv = br[lane + 32 * i], xv = v[i], ov;
        ov.x = (xv.x - mu) * rs * wv.x + bv.x;
        ov.y = (xv.y - mu) * rs * wv.y + bv.y;
        ov.z = (xv.z - mu) * rs * wv.z + bv.z;
        ov.w = (xv.w - mu) * rs * wv.w + bv.w;
        orow[lane + 32 * i] = ov;
    }
}

// ---------------- depthwise causal conv(4) + bias + SiLU ----------------
__global__ void __launch_bounds__(256)
conv_k(const float* __restrict__ xz, const float* __restrict__ cw,
       const float* __restrict__ cb, float* __restrict__ xc)
{
    int idx = blockIdx.x * blockDim.x + threadIdx.x;   // over NTOK*DINNER
    int e = idx & (DINNER - 1);
    int t = idx >> 10;          // token = b*SEQ + l
    int l = t & (SEQ - 1);
    float4 w = ((const float4*)cw)[e];
    const float* base = xz + (size_t)t * (2 * DINNER) + e;  // xi region
    float acc = cb[e] + w.w * base[0];
    if (l >= 1) acc += w.z * base[-(2 * DINNER)];
    if (l >= 2) acc += w.y * base[-2 * (2 * DINNER)];
    if (l >= 3) acc += w.x * base[-3 * (2 * DINNER)];
    xc[idx] = silu_f(acc);
}

// ---------------- tiled fp32 GEMM: C[M,N] = A[M,K] * B[N,K]^T (+epilogue) ----------------
// EPI: 0 = none, 1 = +Res, 2 = softplus(acc + bias[n])
template<int BM, int BN, int BK, int TM, int TN, int EPI>
__global__ void __launch_bounds__((BM/TM)*(BN/TN))
gemm_k(const float* __restrict__ A, int lda,
       const float* __restrict__ B,
       const float* __restrict__ bias,
       const float* __restrict__ Res,
       float* __restrict__ C,
       int M, int N, int K)
{
    constexpr int TH = (BM/TM)*(BN/TN);
    constexpr int MS = TM/4;          // row strips
    constexpr int NS = TN/4;          // col strips
    constexpr int MREG = BM/MS;
    constexpr int NREG = BN/NS;
    __shared__ float As[BK][BM];
    __shared__ float Bs[BK][BN];
    const int tid = threadIdx.x;
    const int tx = tid % (BN/TN);
    const int ty = tid / (BN/TN);
    const int mBase = blockIdx.y * BM;
    const int nBase = blockIdx.x * BN;

    float acc[TM][TN];
#pragma unroll
    for (int i = 0; i < TM; i++)
#pragma unroll
        for (int j = 0; j < TN; j++) acc[i][j] = 0.f;

    for (int k0 = 0; k0 < K; k0 += BK) {
#pragma unroll
        for (int i = tid; i < BM*BK/4; i += TH) {
            int r = i / (BK/4), c = i % (BK/4);
            float4 v = *(const float4*)(A + (size_t)(mBase + r) * lda + k0 + c*4);
            As[c*4+0][r] = v.x; As[c*4+1][r] = v.y;
            As[c*4+2][r] = v.z; As[c*4+3][r] = v.w;
        }
#pragma unroll
        for (int i = tid; i < BN*BK/4; i += TH) {
            int r = i / (BK/4), c = i % (BK/4);
            float4 v = *(const float4*)(B + (size_t)(nBase + r) * K + k0 + c*4);
            Bs[c*4+0][r] = v.x; Bs[c*4+1][r] = v.y;
            Bs[c*4+2][r] = v.z; Bs[c*4+3][r] = v.w;
        }
        __syncthreads();
#pragma unroll
        for (int kk = 0; kk < BK; kk++) {
            float ra[TM], rb[TN];
#pragma unroll
            for (int s = 0; s < MS; s++) {
                float4 v = *(const float4*)&As[kk][s*MREG + ty*4];
                ra[s*4+0] = v.x; ra[s*4+1] = v.y; ra[s*4+2] = v.z; ra[s*4+3] = v.w;
            }
#pragma unroll
            for (int s = 0; s < NS; s++) {
                float4 v = *(const float4*)&Bs[kk][s*NREG + tx*4];
                rb[s*4+0] = v.x; rb[s*4+1] = v.y; rb[s*4+2] = v.z; rb[s*4+3] = v.w;
            }
#pragma unroll
            for (int i = 0; i < TM; i++)
#pragma unroll
                for (int j = 0; j < TN; j++)
                    acc[i][j] = fmaf(ra[i], rb[j], acc[i][j]);
        }
        __syncthreads();
    }

#pragma unroll
    for (int i = 0; i < TM; i++) {
        int m = mBase + (i >> 2) * MREG + ty * 4 + (i & 3);
        float* crow = C + (size_t)m * N;
#pragma unroll
        for (int s = 0; s < NS; s++) {
            int n0 = nBase + s * NREG + tx * 4;
            float4 v = make_float4(acc[i][s*4], acc[i][s*4+1], acc[i][s*4+2], acc[i][s*4+3]);
            if (EPI == 1) {
                float4 r = *(const float4*)(Res + (size_t)m * N + n0);
                v.x += r.x; v.y += r.y; v.z += r.z; v.w += r.w;
            } else if (EPI == 2) {
                float4 bb = *(const float4*)(bias + n0);
                v.x = softplus_f(v.x + bb.x);
                v.y = softplus_f(v.y + bb.y);
                v.z = softplus_f(v.z + bb.z);
                v.w = softplus_f(v.w + bb.w);
            }
            *(float4*)(crow + n0) = v;
        }
    }
}

// ---------------- selective scan: one thread per (b,e), 16 states in regs ----------------
template<bool STRUCT>
__device__ __forceinline__ void scan_body(int b, int e,
    const float* __restrict__ delta, const float* __restrict__ u_,
    const float* __restrict__ dbc,   const float* __restrict__ xz,
    const float* __restrict__ Aneg,  const float* __restrict__ Dp,
    float* __restrict__ y)
{
    float a[DSTATE];
#pragma unroll
    for (int n = 0; n < DSTATE; n++) a[n] = Aneg[e * DSTATE + n];
    float a0 = a[0];
    float Dv = Dp[e];
    float h[DSTATE];
#pragma unroll
    for (int n = 0; n < DSTATE; n++) h[n] = 0.f;

    size_t tb = (size_t)b * SEQ;
    const float* dp = delta + tb * DINNER + e;
    const float* up = u_    + tb * DINNER + e;
    const float* zp = xz    + tb * (2*DINNER) + DINNER + e;
    const float4* bc = (const float4*)(dbc + tb * 64);
    float* yp = y + tb * DINNER + e;

    for (int l = 0; l < SEQ; l++) {
        float d  = __ldg(dp + (size_t)l * DINNER);
        float uu = __ldg(up + (size_t)l * DINNER);
        float zz = __ldg(zp + (size_t)l * (2*DINNER));
        float4 B0 = bc[l*16+ 8], B1 = bc[l*16+ 9], B2 = bc[l*16+10], B3 = bc[l*16+11];
        float4 C0 = bc[l*16+12], C1 = bc[l*16+13], C2 = bc[l*16+14], C3 = bc[l*16+15];
        float Bv[16] = {B0.x,B0.y,B0.z,B0.w, B1.x,B1.y,B1.z,B1.w,
                        B2.x,B2.y,B2.z,B2.w, B3.x,B3.y,B3.z,B3.w};
        float Cv[16] = {C0.x,C0.y,C0.z,C0.w, C1.x,C1.y,C1.z,C1.w,
                        C2.x,C2.y,C2.z,C2.w, C3.x,C3.y,C3.z,C3.w};
        float dA[16];
        if (STRUCT) {
            // A[e][n] == (n+1)*a0  =>  exp(d*A_n) = p^(n+1), p = exp(a0*d)
            float p1 = __expf(a0 * d);
            float p2 = p1*p1, p3 = p2*p1, p4 = p2*p2;
            float p5 = p4*p1, p6 = p4*p2, p7 = p4*p3, p8 = p4*p4;
            dA[0]=p1; dA[1]=p2; dA[2]=p3; dA[3]=p4;
            dA[4]=p5; dA[5]=p6; dA[6]=p7; dA[7]=p8;
            dA[8]=p8*p1; dA[9]=p8*p2; dA[10]=p8*p3; dA[11]=p8*p4;
            dA[12]=p8*p5; dA[13]=p8*p6; dA[14]=p8*p7; dA[15]=p8*p8;
        } else {
#pragma unroll
            for (int n = 0; n < 16; n++) dA[n] = __expf(a[n] * d);
        }
        float du = d * uu;
#pragma unroll
        for (int n = 0; n < 16; n++)
            h[n] = fmaf(dA[n], h[n], du * Bv[n]);
        float acc0 = 0.f, acc1 = 0.f, acc2 = 0.f, acc3 = 0.f;
#pragma unroll
        for (int n = 0; n < 4; n++) {
            acc0 = fmaf(h[n],      Cv[n],      acc0);
            acc1 = fmaf(h[n + 4],  Cv[n + 4],  acc1);
            acc2 = fmaf(h[n + 8],  Cv[n + 8],  acc2);
            acc3 = fmaf(h[n + 12], Cv[n + 12], acc3);
        }
        float ys = (acc0 + acc1) + (acc2 + acc3);
        yp[(size_t)l * DINNER] = (ys + uu * Dv) * silu_f(zz);
    }
}

__global__ void __launch_bounds__(32)
scan_k(const float* __restrict__ delta, const float* __restrict__ u_,
       const float* __restrict__ dbc,   const float* __restrict__ xz,
       const float* __restrict__ Aneg,  const float* __restrict__ Dp,
       const int* __restrict__ flag,    float* __restrict__ y)
{
    int idx = blockIdx.x * 32 + threadIdx.x;   // 0 .. BSZ*DINNER-1
    int b = idx >> 10, e = idx & (DINNER - 1);
    if (*flag == 0)
        scan_body<true >(b, e, delta, u_, dbc, xz, Aneg, Dp, y);
    else
        scan_body<false>(b, e, delta, u_, dbc, xz, Aneg, Dp, y);
}

// ---------------- host launcher ----------------
extern "C" void kernel_launch(void* const* d_in, const int* in_sizes, int n_in,
                              void* d_out, int out_size)
{
    const float* x    = (const float*)d_in[0];
    const float* lnw  = (const float*)d_in[1];
    const float* lnb  = (const float*)d_in[2];
    const float* inw  = (const float*)d_in[3];
    const float* cw   = (const float*)d_in[4];
    const float* cb   = (const float*)d_in[5];
    const float* xpw  = (const float*)d_in[6];
    const float* dtw  = (const float*)d_in[7];
    const float* dtb  = (const float*)d_in[8];
    const float* alog = (const float*)d_in[9];
    const float* dpar = (const float*)d_in[10];
    const float* ow   = (const float*)d_in[11];

    float *xn, *xz, *xc, *dbc, *del, *y, *x1, *an; int* fl;
    cudaGetSymbolAddress((void**)&xn,  g_xn);
    cudaGetSymbolAddress((void**)&xz,  g_xz);
    cudaGetSymbolAddress((void**)&xc,  g_xc);
    cudaGetSymbolAddress((void**)&dbc, g_dbc);
    cudaGetSymbolAddress((void**)&del, g_delta);
    cudaGetSymbolAddress((void**)&y,   g_y);
    cudaGetSymbolAddress((void**)&x1,  g_x1);
    cudaGetSymbolAddress((void**)&an,  g_Aneg);
    cudaGetSymbolAddress((void**)&fl,  g_flag);

    init_k<<<1, 32>>>();
    prep_k<<<(DEPTH*DINNER*DSTATE + 255) / 256, 256>>>(alog);

    for (int L = 0; L < DEPTH; L++) {
        const float* xin  = (L == 0) ? x : x1;
        float*       xout = (L == DEPTH - 1) ? (float*)d_out : x1;

        // 1. LayerNorm
        ln_k<<<NTOK / 8, 256>>>(xin, lnw + L*DMODEL, lnb + L*DMODEL, xn);

        // 2. in_proj: [NTOK,512] x [2048,512]^T -> xz
        gemm_k<128,128,16,8,8,0><<<dim3((2*DINNER)/128, NTOK/128), 256>>>(
            xn, DMODEL, inw + (size_t)L*2*DINNER*DMODEL, nullptr, nullptr,
            xz, NTOK, 2*DINNER, DMODEL);

        // 3. depthwise conv + bias + silu -> xc (u)
        conv_k<<<(NTOK*DINNER) / 256, 256>>>(xz, cw + L*DINNER*4, cb + L*DINNER, xc);

        // 4. x_proj: [NTOK,1024] x [64,1024]^T -> dbc
        gemm_k<128,64,16,8,4,0><<<dim3(1, NTOK/128), 256>>>(
            xc, DINNER, xpw + (size_t)L*64*DINNER, nullptr, nullptr,
            dbc, NTOK, 64, DINNER);

        // 5. dt_proj + softplus: dt(dbc[:, :32], lda=64) x [1024,32]^T -> delta
        gemm_k<128,128,16,8,8,2><<<dim3(DINNER/128, NTOK/128), 256>>>(
            dbc, 64, dtw + (size_t)L*DINNER*DTRANK, dtb + L*DINNER, nullptr,
            del, NTOK, DINNER, DTRANK);

        // 6. selective scan + D-skip + silu(z) gate -> y
        scan_k<<<(BSZ*DINNER) / 32, 32>>>(del, xc, dbc, xz,
            an + L*DINNER*DSTATE, dpar + L*DINNER, fl + L, y);

        // 7. out_proj + residual: xout = xin + y x [512,1024]^T
        gemm_k<128,128,16,8,8,1><<<dim3(DMODEL/128, NTOK/128), 256>>>(
            y, DINNER, ow + (size_t)L*DMODEL*DINNER, nullptr, xin,
            xout, NTOK, DMODEL, DINNER);
    }
}

// round 7
// speedup vs baseline: 1.3179x; 1.3179x over previous
#include <cuda_runtime.h>
#include <cuda_bf16.h>
#include <cstdint>

#define DMODEL 512
#define DINNER 1024
#define DSTATE 16
#define DTRANK 32
#define BSZ 8
#define SEQ 2048
#define NTOK (BSZ*SEQ)      /* 16384 tokens */
#define DEPTH 2

// ---------------- scratch (device globals; no allocation allowed) ----------------
__device__ float g_xn[NTOK*DMODEL];                 // layernorm output
__device__ float g_xz[NTOK*2*DINNER];               // in_proj output (xi | z)
__device__ float g_xc[NTOK*DINNER];                 // conv+silu output (u)
__device__ float g_dbc[NTOK*64];                    // x_proj output (dt|B|C)
__device__ float g_delta[NTOK*DINNER];              // softplus(dt@dtw + dtb)
__device__ float g_y[NTOK*DINNER];                  // scan output (gated)
__device__ float g_x1[NTOK*DMODEL];                 // residual stream after layer0
__device__ float g_Aneg[DEPTH*DINNER*DSTATE];       // A = -exp(A_log)
__device__ int   g_flag[DEPTH];                     // 0 => A[e][n]==(n+1)*A[e][0]

// ---------------- small helpers ----------------
__device__ __forceinline__ float softplus_f(float v) {
    return (v > 20.f) ? v : log1pf(expf(v));
}
__device__ __forceinline__ float silu_f(float v) {
    return __fdividef(v, 1.f + __expf(-v));
}
__device__ __forceinline__ uint32_t smem_u32(const void* p) {
    uint32_t a;
    asm("{ .reg .u64 t; cvta.to.shared.u64 t, %1; cvt.u32.u64 %0, t; }" : "=r"(a) : "l"(p));
    return a;
}

// ldmatrix x4: lanes 0-7 -> matrix0 rows, 8-15 -> m1, 16-23 -> m2, 24-31 -> m3
#define LDSM4(R, addr)                                                        \
    asm volatile("ldmatrix.sync.aligned.m8n8.x4.shared.b16 {%0,%1,%2,%3}, [%4];" \
        : "=r"((R)[0]), "=r"((R)[1]), "=r"((R)[2]), "=r"((R)[3]) : "r"(addr))

#define MMA16816(Cc, Aa, B0, B1)                                              \
    asm volatile("mma.sync.aligned.m16n8k16.row.col.f32.bf16.bf16.f32 "       \
        "{%0,%1,%2,%3}, {%4,%5,%6,%7}, {%8,%9}, {%0,%1,%2,%3};"               \
        : "+f"((Cc)[0]), "+f"((Cc)[1]), "+f"((Cc)[2]), "+f"((Cc)[3])          \
        : "r"((Aa)[0]), "r"((Aa)[1]), "r"((Aa)[2]), "r"((Aa)[3]),             \
          "r"(B0), "r"(B1))

// split two fp32 into packed bf16 hi pair + lo (residual) pair
__device__ __forceinline__ void split2(float a, float b, uint32_t& h, uint32_t& l) {
    __nv_bfloat162 hb = __float22bfloat162_rn(make_float2(a, b));
    float ra = a - __bfloat162float(hb.x);
    float rb = b - __bfloat162float(hb.y);
    __nv_bfloat162 lb = __float22bfloat162_rn(make_float2(ra, rb));
    h = *(uint32_t*)&hb;
    l = *(uint32_t*)&lb;
}

// ---------------- init / precompute ----------------
__global__ void init_k() {
    if (threadIdx.x < DEPTH) g_flag[threadIdx.x] = 0;
}

__global__ void prep_k(const float* __restrict__ Alog) {
    int idx = blockIdx.x * blockDim.x + threadIdx.x;
    if (idx >= DEPTH * DINNER * DSTATE) return;
    float a = -expf(Alog[idx]);
    g_Aneg[idx] = a;
    int n = idx & 15;
    float a0 = -expf(Alog[idx & ~15]);
    if (fabsf(a - (float)(n + 1) * a0) > 1e-4f * fabsf(a) + 1e-12f)
        atomicOr(&g_flag[idx >> 14], 1);
}

// ---------------- LayerNorm: one warp per token ----------------
__global__ void __launch_bounds__(256)
ln_k(const float* __restrict__ x, const float* __restrict__ w,
     const float* __restrict__ b, float* __restrict__ o)
{
    int token = blockIdx.x * (blockDim.x >> 5) + (threadIdx.x >> 5);
    int lane = threadIdx.x & 31;
    const float4* xr = (const float4*)(x + (size_t)token * DMODEL);
    float4 v[4];
    float s = 0.f, sq = 0.f;
#pragma unroll
    for (int i = 0; i < 4; i++) {
        v[i] = xr[lane + 32 * i];
        s  += v[i].x + v[i].y + v[i].z + v[i].w;
        sq += v[i].x*v[i].x + v[i].y*v[i].y + v[i].z*v[i].z + v[i].w*v[i].w;
    }
#pragma unroll
    for (int off = 16; off; off >>= 1) {
        s  += __shfl_xor_sync(0xffffffffu, s,  off);
        sq += __shfl_xor_sync(0xffffffffu, sq, off);
    }
    float mu  = s * (1.f / DMODEL);
    float var = sq * (1.f / DMODEL) - mu * mu;
    float rs  = rsqrtf(var + 1e-5f);
    const float4* wr = (const float4*)w;
    const float4* br = (const float4*)b;
    float4* orow = (float4*)(o + (size_t)token * DMODEL);
#pragma unroll
    for (int i = 0; i < 4; i++) {
        float4 wv = wr[lane + 32 * i], bv = br[lane + 32 * i], xv = v[i], ov;
        ov.x = (xv.x - mu) * rs * wv.x + bv.x;
        ov.y = (xv.y - mu) * rs * wv.y + bv.y;
        ov.z = (xv.z - mu) * rs * wv.z + bv.z;
        ov.w = (xv.w - mu) * rs * wv.w + bv.w;
        orow[lane + 32 * i] = ov;
    }
}

// ---------------- depthwise causal conv(4) + bias + SiLU ----------------
__global__ void __launch_bounds__(256)
conv_k(const float* __restrict__ xz, const float* __restrict__ cw,
       const float* __restrict__ cb, float* __restrict__ xc)
{
    int idx = blockIdx.x * blockDim.x + threadIdx.x;
    int e = idx & (DINNER - 1);
    int t = idx >> 10;
    int l = t & (SEQ - 1);
    float4 w = ((const float4*)cw)[e];
    const float* base = xz + (size_t)t * (2 * DINNER) + e;
    float acc = cb[e] + w.w * base[0];
    if (l >= 1) acc += w.z * base[-(2 * DINNER)];
    if (l >= 2) acc += w.y * base[-2 * (2 * DINNER)];
    if (l >= 3) acc += w.x * base[-3 * (2 * DINNER)];
    xc[idx] = silu_f(acc);
}

// ---------------- bf16-split tensor-core GEMM via mma.sync ----------------
// C[M,N] = A[M,K] * B[N,K]^T (+epilogue). BM=128, BK=32, BN in {64,128}.
// 2-term bf16 split (hi+lo): 3 MMAs per fragment pair.
// EPI: 0 = none, 1 = +Res, 2 = softplus(acc + bias[n])
template<int BN, int EPI>
__global__ void __launch_bounds__(256, 1)
mma_gemm(const float* __restrict__ A, int lda,
         const float* __restrict__ B,
         const float* __restrict__ bias,
         const float* __restrict__ Res,
         float* __restrict__ C,
         int M, int N, int K)
{
    constexpr int RS = 40;                    // smem row stride (bf16): 80B, odd*16B -> conflict-free ldmatrix
    constexpr int WY = (BN == 128) ? 2 : 4;   // warps stacked along M
    constexpr int WM = 128 / WY;              // warp M tile
    constexpr int MF = WM / 16;               // A fragments per warp (4 or 2)
    constexpr int PB = BN / 32;               // per-thread B float4 loads per chunk

    __shared__ __align__(16) uint16_t sAh[128 * RS], sAl[128 * RS];
    __shared__ __align__(16) uint16_t sBh[BN  * RS], sBl[BN  * RS];

    const int tid = threadIdx.x, lane = tid & 31, wid = tid >> 5;
    const int wy = wid % WY, wx = wid / WY;
    const int mBase = blockIdx.y * 128, nBase = blockIdx.x * BN;

    float acc[MF][4][4];
#pragma unroll
    for (int i = 0; i < MF; i++)
#pragma unroll
        for (int j = 0; j < 4; j++)
#pragma unroll
            for (int t = 0; t < 4; t++) acc[i][j][t] = 0.f;

    // per-thread gmem load coordinates (fixed): row = lr + 32*i, col = lc..lc+3
    const int lr = tid >> 3;
    const int lc = (tid & 7) * 4;

    float4 pa[4], pb[PB];
#pragma unroll
    for (int i = 0; i < 4; i++)
        pa[i] = *(const float4*)(A + (size_t)(mBase + lr + 32 * i) * lda + lc);
#pragma unroll
    for (int i = 0; i < PB; i++)
        pb[i] = *(const float4*)(B + (size_t)(nBase + lr + 32 * i) * K + lc);

    const int nch = K >> 5;
    for (int c = 0; c < nch; c++) {
        if (c) __syncthreads();              // previous compute done before overwrite
        // convert + store current chunk
#pragma unroll
        for (int i = 0; i < 4; i++) {
            uint32_t h0, l0, h1, l1;
            split2(pa[i].x, pa[i].y, h0, l0);
            split2(pa[i].z, pa[i].w, h1, l1);
            int off = (lr + 32 * i) * RS + lc;
            *(uint2*)(sAh + off) = make_uint2(h0, h1);
            *(uint2*)(sAl + off) = make_uint2(l0, l1);
        }
#pragma unroll
        for (int i = 0; i < PB; i++) {
            uint32_t h0, l0, h1, l1;
            split2(pb[i].x, pb[i].y, h0, l0);
            split2(pb[i].z, pb[i].w, h1, l1);
            int off = (lr + 32 * i) * RS + lc;
            *(uint2*)(sBh + off) = make_uint2(h0, h1);
            *(uint2*)(sBl + off) = make_uint2(l0, l1);
        }
        __syncthreads();

        // prefetch next chunk into regs while MMAs run
        if (c + 1 < nch) {
            int k0 = (c + 1) << 5;
#pragma unroll
            for (int i = 0; i < 4; i++)
                pa[i] = *(const float4*)(A + (size_t)(mBase + lr + 32 * i) * lda + k0 + lc);
#pragma unroll
            for (int i = 0; i < PB; i++)
                pb[i] = *(const float4*)(B + (size_t)(nBase + lr + 32 * i) * K + k0 + lc);
        }

        const int q = lane >> 3, rr = lane & 7;
#pragma unroll
        for (int ks = 0; ks < 2; ks++) {
            uint32_t ah[MF][4], al[MF][4], bh[2][4], bl[2][4];
#pragma unroll
            for (int i = 0; i < MF; i++) {
                int row = wy * WM + i * 16 + (q & 1) * 8 + rr;
                int col = ks * 16 + (q >> 1) * 8;
                LDSM4(ah[i], smem_u32(sAh + row * RS + col));
                LDSM4(al[i], smem_u32(sAl + row * RS + col));
            }
#pragma unroll
            for (int p = 0; p < 2; p++) {
                int row = wx * 32 + p * 16 + (q >> 1) * 8 + rr;
                int col = ks * 16 + (q & 1) * 8;
                LDSM4(bh[p], smem_u32(sBh + row * RS + col));
                LDSM4(bl[p], smem_u32(sBl + row * RS + col));
            }
#pragma unroll
            for (int i = 0; i < MF; i++)
#pragma unroll
                for (int j = 0; j < 4; j++) {
                    const int p = j >> 1, s = (j & 1) * 2;
                    MMA16816(acc[i][j], ah[i], bh[p][s], bh[p][s + 1]);
                    MMA16816(acc[i][j], ah[i], bl[p][s], bl[p][s + 1]);
                    MMA16816(acc[i][j], al[i], bh[p][s], bh[p][s + 1]);
                }
        }
    }

    // ---------------- epilogue ----------------
#pragma unroll
    for (int i = 0; i < MF; i++) {
        int row0 = mBase + wy * WM + i * 16 + (lane >> 2);
#pragma unroll
        for (int j = 0; j < 4; j++) {
            int col = nBase + wx * 32 + j * 8 + (lane & 3) * 2;
#pragma unroll
            for (int hhalf = 0; hhalf < 2; hhalf++) {
                int row = row0 + hhalf * 8;
                float2 v = make_float2(acc[i][j][2 * hhalf], acc[i][j][2 * hhalf + 1]);
                if (EPI == 1) {
                    float2 r = *(const float2*)(Res + (size_t)row * N + col);
                    v.x += r.x; v.y += r.y;
                } else if (EPI == 2) {
                    float2 bb = *(const float2*)(bias + col);
                    v.x = softplus_f(v.x + bb.x);
                    v.y = softplus_f(v.y + bb.y);
                }
                *(float2*)(C + (size_t)row * N + col) = v;
            }
        }
    }
}

// ---------------- selective scan: 4-thread quad per (b,e), 4 states/thread ----------------
template<bool STRUCT>
__device__ __forceinline__ void scan4_body(int b, int e, int q,
    const float* __restrict__ delta, const float* __restrict__ u_,
    const float* __restrict__ dbc,   const float* __restrict__ xz,
    const float* __restrict__ Aneg,  const float* __restrict__ Dp,
    float* __restrict__ y)
{
    float a0v = Aneg[e * DSTATE + q * 4 + 0];
    float a1v = Aneg[e * DSTATE + q * 4 + 1];
    float a2v = Aneg[e * DSTATE + q * 4 + 2];
    float a3v = Aneg[e * DSTATE + q * 4 + 3];
    float a0 = Aneg[e * DSTATE];
    float Dv = Dp[e];
    float h0 = 0.f, h1 = 0.f, h2 = 0.f, h3 = 0.f;

    size_t tb = (size_t)b * SEQ;
    const float* dp = delta + tb * DINNER + e;
    const float* up = u_    + tb * DINNER + e;
    const float* zp = xz    + tb * (2*DINNER) + DINNER + e;
    const float4* bc = (const float4*)(dbc + tb * 64);
    float* yp = y + tb * DINNER + e;

    for (int l = 0; l < SEQ; l++) {
        float d  = __ldg(dp + (size_t)l * DINNER);
        float uu = __ldg(up + (size_t)l * DINNER);
        float zz = __ldg(zp + (size_t)l * (2*DINNER));
        float4 Bq = __ldg(bc + l * 16 + 8  + q);
        float4 Cq = __ldg(bc + l * 16 + 12 + q);
        float dA0, dA1, dA2, dA3;
        if (STRUCT) {
            float p  = __expf(a0 * d);
            float p2 = p * p, p3 = p2 * p, p4 = p2 * p2;
            float p8 = p4 * p4;
            float p4q = 1.f;
            if (q & 1) p4q = p4;
            if (q & 2) p4q *= p8;
            dA0 = p4q * p; dA1 = p4q * p2; dA2 = p4q * p3; dA3 = p4q * p4;
        } else {
            dA0 = __expf(a0v * d); dA1 = __expf(a1v * d);
            dA2 = __expf(a2v * d); dA3 = __expf(a3v * d);
        }
        float du = d * uu;
        h0 = fmaf(dA0, h0, du * Bq.x);
        h1 = fmaf(dA1, h1, du * Bq.y);
        h2 = fmaf(dA2, h2, du * Bq.z);
        h3 = fmaf(dA3, h3, du * Bq.w);
        float r = fmaf(h0, Cq.x, fmaf(h1, Cq.y, fmaf(h2, Cq.z, h3 * Cq.w)));
        r += __shfl_xor_sync(0xffffffffu, r, 1);
        r += __shfl_xor_sync(0xffffffffu, r, 2);
        if (q == 0)
            yp[(size_t)l * DINNER] = (r + uu * Dv) * silu_f(zz);
    }
}

__global__ void __launch_bounds__(128)
scan_k(const float* __restrict__ delta, const float* __restrict__ u_,
       const float* __restrict__ dbc,   const float* __restrict__ xz,
       const float* __restrict__ Aneg,  const float* __restrict__ Dp,
       const int* __restrict__ flag,    float* __restrict__ y)
{
    int idx = blockIdx.x * 128 + threadIdx.x;   // 0 .. BSZ*DINNER*4-1
    int q = idx & 3;
    int chain = idx >> 2;
    int e = chain & (DINNER - 1);
    int b = chain >> 10;
    if (*flag == 0)
        scan4_body<true >(b, e, q, delta, u_, dbc, xz, Aneg, Dp, y);
    else
        scan4_body<false>(b, e, q, delta, u_, dbc, xz, Aneg, Dp, y);
}

// ---------------- host launcher ----------------
extern "C" void kernel_launch(void* const* d_in, const int* in_sizes, int n_in,
                              void* d_out, int out_size)
{
    const float* x    = (const float*)d_in[0];
    const float* lnw  = (const float*)d_in[1];
    const float* lnb  = (const float*)d_in[2];
    const float* inw  = (const float*)d_in[3];
    const float* cw   = (const float*)d_in[4];
    const float* cb   = (const float*)d_in[5];
    const float* xpw  = (const float*)d_in[6];
    const float* dtw  = (const float*)d_in[7];
    const float* dtb  = (const float*)d_in[8];
    const float* alog = (const float*)d_in[9];
    const float* dpar = (const float*)d_in[10];
    const float* ow   = (const float*)d_in[11];

    float *xn, *xz, *xc, *dbc, *del, *y, *x1, *an; int* fl;
    cudaGetSymbolAddress((void**)&xn,  g_xn);
    cudaGetSymbolAddress((void**)&xz,  g_xz);
    cudaGetSymbolAddress((void**)&xc,  g_xc);
    cudaGetSymbolAddress((void**)&dbc, g_dbc);
    cudaGetSymbolAddress((void**)&del, g_delta);
    cudaGetSymbolAddress((void**)&y,   g_y);
    cudaGetSymbolAddress((void**)&x1,  g_x1);
    cudaGetSymbolAddress((void**)&an,  g_Aneg);
    cudaGetSymbolAddress((void**)&fl,  g_flag);

    init_k<<<1, 32>>>();
    prep_k<<<(DEPTH*DINNER*DSTATE + 255) / 256, 256>>>(alog);

    for (int L = 0; L < DEPTH; L++) {
        const float* xin  = (L == 0) ? x : x1;
        float*       xout = (L == DEPTH - 1) ? (float*)d_out : x1;

        // 1. LayerNorm
        ln_k<<<NTOK / 8, 256>>>(xin, lnw + L*DMODEL, lnb + L*DMODEL, xn);

        // 2. in_proj: [16384,512] x [2048,512]^T -> xz
        mma_gemm<128, 0><<<dim3(2*DINNER/128, NTOK/128), 256>>>(
            xn, DMODEL, inw + (size_t)L*2*DINNER*DMODEL, nullptr, nullptr,
            xz, NTOK, 2*DINNER, DMODEL);

        // 3. depthwise conv + bias + silu -> xc (u)
        conv_k<<<(NTOK*DINNER) / 256, 256>>>(xz, cw + L*DINNER*4, cb + L*DINNER, xc);

        // 4. x_proj: [16384,1024] x [64,1024]^T -> dbc
        mma_gemm<64, 0><<<dim3(1, NTOK/128), 256>>>(
            xc, DINNER, xpw + (size_t)L*64*DINNER, nullptr, nullptr,
            dbc, NTOK, 64, DINNER);

        // 5. dt_proj + softplus: dbc[:, :32] (lda=64) x [1024,32]^T -> delta
        mma_gemm<128, 2><<<dim3(DINNER/128, NTOK/128), 256>>>(
            dbc, 64, dtw + (size_t)L*DINNER*DTRANK, dtb + L*DINNER, nullptr,
            del, NTOK, DINNER, DTRANK);

        // 6. selective scan + D-skip + silu(z) gate -> y
        scan_k<<<(BSZ*DINNER*4) / 128, 128>>>(del, xc, dbc, xz,
            an + L*DINNER*DSTATE, dpar + L*DINNER, fl + L, y);

        // 7. out_proj + residual: xout = xin + y x [512,1024]^T
        mma_gemm<128, 1><<<dim3(DMODEL/128, NTOK/128), 256>>>(
            y, DINNER, ow + (size_t)L*DMODEL*DINNER, nullptr, xin,
            xout, NTOK, DMODEL, DINNER);
    }
}

// round 9
// speedup vs baseline: 1.7578x; 1.3338x over previous
#include <cuda_runtime.h>
#include <cuda_bf16.h>
#include <cstdint>

#define DMODEL 512
#define DINNER 1024
#define DSTATE 16
#define DTRANK 32
#define BSZ 8
#define SEQ 2048
#define NTOK (BSZ*SEQ)      /* 16384 tokens */
#define DEPTH 2

// ---------------- scratch (device globals; no allocation allowed) ----------------
__device__ float g_xn[NTOK*DMODEL];                 // layernorm output
__device__ float g_xz[NTOK*2*DINNER];               // in_proj output (xi | z)
__device__ float g_xc[NTOK*DINNER];                 // conv+silu output (u)
__device__ float g_dbc[NTOK*64];                    // x_proj output (dt|B|C)
__device__ float g_delta[NTOK*DINNER];              // softplus(dt@dtw + dtb)
__device__ float g_y[NTOK*DINNER];                  // scan output (gated)
__device__ float g_x1[NTOK*DMODEL];                 // residual stream after layer0
__device__ float g_Aneg[DEPTH*DINNER*DSTATE];       // A = -exp(A_log)
__device__ int   g_flag[DEPTH];                     // 0 => A[e][n]==(n+1)*A[e][0]

// ---------------- small helpers ----------------
__device__ __forceinline__ float softplus_f(float v) {
    return (v > 20.f) ? v : log1pf(expf(v));
}
__device__ __forceinline__ float silu_f(float v) {
    return __fdividef(v, 1.f + __expf(-v));
}
__device__ __forceinline__ uint32_t smem_u32(const void* p) {
    uint32_t a;
    asm("{ .reg .u64 t; cvta.to.shared.u64 t, %1; cvt.u32.u64 %0, t; }" : "=r"(a) : "l"(p));
    return a;
}

// ldmatrix x4: lanes 0-7 -> matrix0 rows, 8-15 -> m1, 16-23 -> m2, 24-31 -> m3
#define LDSM4(R, addr)                                                        \
    asm volatile("ldmatrix.sync.aligned.m8n8.x4.shared.b16 {%0,%1,%2,%3}, [%4];" \
        : "=r"((R)[0]), "=r"((R)[1]), "=r"((R)[2]), "=r"((R)[3]) : "r"(addr))

#define MMA16816(Cc, Aa, B0, B1)                                              \
    asm volatile("mma.sync.aligned.m16n8k16.row.col.f32.bf16.bf16.f32 "       \
        "{%0,%1,%2,%3}, {%4,%5,%6,%7}, {%8,%9}, {%0,%1,%2,%3};"               \
        : "+f"((Cc)[0]), "+f"((Cc)[1]), "+f"((Cc)[2]), "+f"((Cc)[3])          \
        : "r"((Aa)[0]), "r"((Aa)[1]), "r"((Aa)[2]), "r"((Aa)[3]),             \
          "r"(B0), "r"(B1))

// split two fp32 into packed bf16 hi pair + lo (residual) pair
__device__ __forceinline__ void split2(float a, float b, uint32_t& h, uint32_t& l) {
    __nv_bfloat162 hb = __float22bfloat162_rn(make_float2(a, b));
    float ra = a - __bfloat162float(hb.x);
    float rb = b - __bfloat162float(hb.y);
    __nv_bfloat162 lb = __float22bfloat162_rn(make_float2(ra, rb));
    h = *(uint32_t*)&hb;
    l = *(uint32_t*)&lb;
}

// ---------------- init / precompute ----------------
__global__ void init_k() {
    if (threadIdx.x < DEPTH) g_flag[threadIdx.x] = 0;
}

__global__ void prep_k(const float* __restrict__ Alog) {
    int idx = blockIdx.x * blockDim.x + threadIdx.x;
    if (idx >= DEPTH * DINNER * DSTATE) return;
    float a = -expf(Alog[idx]);
    g_Aneg[idx] = a;
    int n = idx & 15;
    float a0 = -expf(Alog[idx & ~15]);
    if (fabsf(a - (float)(n + 1) * a0) > 1e-4f * fabsf(a) + 1e-12f)
        atomicOr(&g_flag[idx >> 14], 1);
}

// ---------------- LayerNorm: one warp per token ----------------
__global__ void __launch_bounds__(256)
ln_k(const float* __restrict__ x, const float* __restrict__ w,
     const float* __restrict__ b, float* __restrict__ o)
{
    int token = blockIdx.x * (blockDim.x >> 5) + (threadIdx.x >> 5);
    int lane = threadIdx.x & 31;
    const float4* xr = (const float4*)(x + (size_t)token * DMODEL);
    float4 v[4];
    float s = 0.f, sq = 0.f;
#pragma unroll
    for (int i = 0; i < 4; i++) {
        v[i] = xr[lane + 32 * i];
        s  += v[i].x + v[i].y + v[i].z + v[i].w;
        sq += v[i].x*v[i].x + v[i].y*v[i].y + v[i].z*v[i].z + v[i].w*v[i].w;
    }
#pragma unroll
    for (int off = 16; off; off >>= 1) {
        s  += __shfl_xor_sync(0xffffffffu, s,  off);
        sq += __shfl_xor_sync(0xffffffffu, sq, off);
    }
    float mu  = s * (1.f / DMODEL);
    float var = sq * (1.f / DMODEL) - mu * mu;
    float rs  = rsqrtf(var + 1e-5f);
    const float4* wr = (const float4*)w;
    const float4* br = (const float4*)b;
    float4* orow = (float4*)(o + (size_t)token * DMODEL);
#pragma unroll
    for (int i = 0; i < 4; i++) {
        float4 wv = wr[lane + 32 * i], bv = br[lane + 32 * i], xv = v[i], ov;
        ov.x = (xv.x - mu) * rs * wv.x + bv.x;
        ov.y = (xv.y - mu) * rs * wv.y + bv.y;
        ov.z = (xv.z - mu) * rs * wv.z + bv.z;
        ov.w = (xv.w - mu) * rs * wv.w + bv.w;
        orow[lane + 32 * i] = ov;
    }
}

// ---------------- depthwise causal conv(4) + bias + SiLU ----------------
__global__ void __launch_bounds__(256)
conv_k(const float* __restrict__ xz, const float* __restrict__ cw,
       const float* __restrict__ cb, float* __restrict__ xc)
{
    int idx = blockIdx.x * blockDim.x + threadIdx.x;
    int e = idx & (DINNER - 1);
    int t = idx >> 10;
    int l = t & (SEQ - 1);
    float4 w = ((const float4*)cw)[e];
    const float* base = xz + (size_t)t * (2 * DINNER) + e;
    float acc = cb[e] + w.w * base[0];
    if (l >= 1) acc += w.z * base[-(2 * DINNER)];
    if (l >= 2) acc += w.y * base[-2 * (2 * DINNER)];
    if (l >= 3) acc += w.x * base[-3 * (2 * DINNER)];
    xc[idx] = silu_f(acc);
}

// ---------------- bf16-split tensor-core GEMM via mma.sync ----------------
// C[M,N] = A[M,K] * B[N,K]^T (+epilogue). BM=128, BK=32, BN in {64,128}.
// 2-term bf16 split (hi+lo): 3 MMAs per fragment pair.
// EPI: 0 = none, 1 = +Res, 2 = softplus(acc + bias[n])
template<int BN, int EPI>
__global__ void __launch_bounds__(256, 1)
mma_gemm(const float* __restrict__ A, int lda,
         const float* __restrict__ B,
         const float* __restrict__ bias,
         const float* __restrict__ Res,
         float* __restrict__ C,
         int M, int N, int K)
{
    constexpr int RS = 40;                    // smem row stride (bf16): 80B, odd*16B -> conflict-free ldmatrix
    constexpr int WY = (BN == 128) ? 2 : 4;   // warps stacked along M
    constexpr int WM = 128 / WY;              // warp M tile
    constexpr int MF = WM / 16;               // A fragments per warp (4 or 2)
    constexpr int PB = BN / 32;               // per-thread B float4 loads per chunk

    __shared__ __align__(16) uint16_t sAh[128 * RS], sAl[128 * RS];
    __shared__ __align__(16) uint16_t sBh[BN  * RS], sBl[BN  * RS];

    const int tid = threadIdx.x, lane = tid & 31, wid = tid >> 5;
    const int wy = wid % WY, wx = wid / WY;
    const int mBase = blockIdx.y * 128, nBase = blockIdx.x * BN;

    float acc[MF][4][4];
#pragma unroll
    for (int i = 0; i < MF; i++)
#pragma unroll
        for (int j = 0; j < 4; j++)
#pragma unroll
            for (int t = 0; t < 4; t++) acc[i][j][t] = 0.f;

    // per-thread gmem load coordinates (fixed): row = lr + 32*i, col = lc..lc+3
    const int lr = tid >> 3;
    const int lc = (tid & 7) * 4;

    float4 pa[4], pb[PB];
#pragma unroll
    for (int i = 0; i < 4; i++)
        pa[i] = *(const float4*)(A + (size_t)(mBase + lr + 32 * i) * lda + lc);
#pragma unroll
    for (int i = 0; i < PB; i++)
        pb[i] = *(const float4*)(B + (size_t)(nBase + lr + 32 * i) * K + lc);

    const int nch = K >> 5;
    for (int c = 0; c < nch; c++) {
        if (c) __syncthreads();              // previous compute done before overwrite
        // convert + store current chunk
#pragma unroll
        for (int i = 0; i < 4; i++) {
            uint32_t h0, l0, h1, l1;
            split2(pa[i].x, pa[i].y, h0, l0);
            split2(pa[i].z, pa[i].w, h1, l1);
            int off = (lr + 32 * i) * RS + lc;
            *(uint2*)(sAh + off) = make_uint2(h0, h1);
            *(uint2*)(sAl + off) = make_uint2(l0, l1);
        }
#pragma unroll
        for (int i = 0; i < PB; i++) {
            uint32_t h0, l0, h1, l1;
            split2(pb[i].x, pb[i].y, h0, l0);
            split2(pb[i].z, pb[i].w, h1, l1);
            int off = (lr + 32 * i) * RS + lc;
            *(uint2*)(sBh + off) = make_uint2(h0, h1);
            *(uint2*)(sBl + off) = make_uint2(l0, l1);
        }
        __syncthreads();

        // prefetch next chunk into regs while MMAs run
        if (c + 1 < nch) {
            int k0 = (c + 1) << 5;
#pragma unroll 4
            for (int i = 0; i < 4; i++)
                pa[i] = *(const float4*)(A + (size_t)(mBase + lr + 32 * i) * lda + k0 + lc);
#pragma unroll
            for (int i = 0; i < PB; i++)
                pb[i] = *(const float4*)(B + (size_t)(nBase + lr + 32 * i) * K + k0 + lc);
        }

        const int q = lane >> 3, rr = lane & 7;
#pragma unroll
        for (int ks = 0; ks < 2; ks++) {
            uint32_t ah[MF][4], al[MF][4], bh[2][4], bl[2][4];
#pragma unroll
            for (int i = 0; i < MF; i++) {
                int row = wy * WM + i * 16 + (q & 1) * 8 + rr;
                int col = ks * 16 + (q >> 1) * 8;
                LDSM4(ah[i], smem_u32(sAh + row * RS + col));
                LDSM4(al[i], smem_u32(sAl + row * RS + col));
            }
#pragma unroll
            for (int p = 0; p < 2; p++) {
                int row = wx * 32 + p * 16 + (q >> 1) * 8 + rr;
                int col = ks * 16 + (q & 1) * 8;
                LDSM4(bh[p], smem_u32(sBh + row * RS + col));
                LDSM4(bl[p], smem_u32(sBl + row * RS + col));
            }
#pragma unroll
            for (int i = 0; i < MF; i++)
#pragma unroll
                for (int j = 0; j < 4; j++) {
                    const int p = j >> 1, s = (j & 1) * 2;
                    MMA16816(acc[i][j], ah[i], bh[p][s], bh[p][s + 1]);
                    MMA16816(acc[i][j], ah[i], bl[p][s], bl[p][s + 1]);
                    MMA16816(acc[i][j], al[i], bh[p][s], bh[p][s + 1]);
                }
        }
    }

    // ---------------- epilogue ----------------
#pragma unroll
    for (int i = 0; i < MF; i++) {
        int row0 = mBase + wy * WM + i * 16 + (lane >> 2);
#pragma unroll
        for (int j = 0; j < 4; j++) {
            int col = nBase + wx * 32 + j * 8 + (lane & 3) * 2;
#pragma unroll
            for (int hhalf = 0; hhalf < 2; hhalf++) {
                int row = row0 + hhalf * 8;
                float2 v = make_float2(acc[i][j][2 * hhalf], acc[i][j][2 * hhalf + 1]);
                if (EPI == 1) {
                    float2 r = *(const float2*)(Res + (size_t)row * N + col);
                    v.x += r.x; v.y += r.y;
                } else if (EPI == 2) {
                    float2 bb = *(const float2*)(bias + col);
                    v.x = softplus_f(v.x + bb.x);
                    v.y = softplus_f(v.y + bb.y);
                }
                *(float2*)(C + (size_t)row * N + col) = v;
            }
        }
    }
}

// ---------------- selective scan: 4-thread quad per (b,e), 4 states/thread ----------------
// Software-pipelined: loads for the next 4 timesteps are issued before
// computing the current 4, hiding L2/DRAM latency behind the recurrence.
#define SCAN_PF 4

template<bool STRUCT>
__device__ __forceinline__ void scan4_body(int b, int e, int q,
    const float* __restrict__ delta, const float* __restrict__ u_,
    const float* __restrict__ dbc,   const float* __restrict__ xz,
    const float* __restrict__ Aneg,  const float* __restrict__ Dp,
    float* __restrict__ y)
{
    float a0v = Aneg[e * DSTATE + q * 4 + 0];
    float a1v = Aneg[e * DSTATE + q * 4 + 1];
    float a2v = Aneg[e * DSTATE + q * 4 + 2];
    float a3v = Aneg[e * DSTATE + q * 4 + 3];
    float a0 = Aneg[e * DSTATE];
    float Dv = Dp[e];
    float h0 = 0.f, h1 = 0.f, h2 = 0.f, h3 = 0.f;

    size_t tb = (size_t)b * SEQ;
    const float* dp = delta + tb * DINNER + e;
    const float* up = u_    + tb * DINNER + e;
    const float* zp = xz    + tb * (2*DINNER) + DINNER + e;
    const float4* bc = (const float4*)(dbc + tb * 64);
    float* yp = y + tb * DINNER + e;

    float  db[2][SCAN_PF], ub[2][SCAN_PF], zb[2][SCAN_PF];
    float4 Bb[2][SCAN_PF], Cb[2][SCAN_PF];

    // prologue: load timesteps 0..SCAN_PF-1 into bank 0
#pragma unroll
    for (int j = 0; j < SCAN_PF; j++) {
        db[0][j] = __ldg(dp + (size_t)j * DINNER);
        ub[0][j] = __ldg(up + (size_t)j * DINNER);
        zb[0][j] = __ldg(zp + (size_t)j * (2*DINNER));
        Bb[0][j] = __ldg(bc + j * 16 + 8  + q);
        Cb[0][j] = __ldg(bc + j * 16 + 12 + q);
    }

    int bank = 0;
    for (int l0 = 0; l0 < SEQ; l0 += SCAN_PF) {
        const int nb = bank ^ 1;
        if (l0 + SCAN_PF < SEQ) {
#pragma unroll
            for (int j = 0; j < SCAN_PF; j++) {
                int l = l0 + SCAN_PF + j;
                db[nb][j] = __ldg(dp + (size_t)l * DINNER);
                ub[nb][j] = __ldg(up + (size_t)l * DINNER);
                zb[nb][j] = __ldg(zp + (size_t)l * (2*DINNER));
                Bb[nb][j] = __ldg(bc + l * 16 + 8  + q);
                Cb[nb][j] = __ldg(bc + l * 16 + 12 + q);
            }
        }
#pragma unroll
        for (int j = 0; j < SCAN_PF; j++) {
            float d  = db[bank][j];
            float uu = ub[bank][j];
            float zz = zb[bank][j];
            float4 Bq = Bb[bank][j];
            float4 Cq = Cb[bank][j];
            float dA0, dA1, dA2, dA3;
            if (STRUCT) {
                float p  = __expf(a0 * d);
                float p2 = p * p, p3 = p2 * p, p4 = p2 * p2;
                float p8 = p4 * p4;
                float p4q = 1.f;
                if (q & 1) p4q = p4;
                if (q & 2) p4q *= p8;
                dA0 = p4q * p; dA1 = p4q * p2; dA2 = p4q * p3; dA3 = p4q * p4;
            } else {
                dA0 = __expf(a0v * d); dA1 = __expf(a1v * d);
                dA2 = __expf(a2v * d); dA3 = __expf(a3v * d);
            }
            float du = d * uu;
            h0 = fmaf(dA0, h0, du * Bq.x);
            h1 = fmaf(dA1, h1, du * Bq.y);
            h2 = fmaf(dA2, h2, du * Bq.z);
            h3 = fmaf(dA3, h3, du * Bq.w);
            float r = fmaf(h0, Cq.x, fmaf(h1, Cq.y, fmaf(h2, Cq.z, h3 * Cq.w)));
            r += __shfl_xor_sync(0xffffffffu, r, 1);
            r += __shfl_xor_sync(0xffffffffu, r, 2);
            if (q == 0)
                yp[(size_t)(l0 + j) * DINNER] = (r + uu * Dv) * silu_f(zz);
        }
        bank = nb;
    }
}

__global__ void __launch_bounds__(128)
scan_k(const float* __restrict__ delta, const float* __restrict__ u_,
       const float* __restrict__ dbc,   const float* __restrict__ xz,
       const float* __restrict__ Aneg,  const float* __restrict__ Dp,
       const int* __restrict__ flag,    float* __restrict__ y)
{
    int idx = blockIdx.x * 128 + threadIdx.x;   // 0 .. BSZ*DINNER*4-1
    int q = idx & 3;
    int chain = idx >> 2;
    int e = chain & (DINNER - 1);
    int b = chain >> 10;
    if (*flag == 0)
        scan4_body<true >(b, e, q, delta, u_, dbc, xz, Aneg, Dp, y);
    else
        scan4_body<false>(b, e, q, delta, u_, dbc, xz, Aneg, Dp, y);
}

// ---------------- host launcher ----------------
extern "C" void kernel_launch(void* const* d_in, const int* in_sizes, int n_in,
                              void* d_out, int out_size)
{
    const float* x    = (const float*)d_in[0];
    const float* lnw  = (const float*)d_in[1];
    const float* lnb  = (const float*)d_in[2];
    const float* inw  = (const float*)d_in[3];
    const float* cw   = (const float*)d_in[4];
    const float* cb   = (const float*)d_in[5];
    const float* xpw  = (const float*)d_in[6];
    const float* dtw  = (const float*)d_in[7];
    const float* dtb  = (const float*)d_in[8];
    const float* alog = (const float*)d_in[9];
    const float* dpar = (const float*)d_in[10];
    const float* ow   = (const float*)d_in[11];

    float *xn, *xz, *xc, *dbc, *del, *y, *x1, *an; int* fl;
    cudaGetSymbolAddress((void**)&xn,  g_xn);
    cudaGetSymbolAddress((void**)&xz,  g_xz);
    cudaGetSymbolAddress((void**)&xc,  g_xc);
    cudaGetSymbolAddress((void**)&dbc, g_dbc);
    cudaGetSymbolAddress((void**)&del, g_delta);
    cudaGetSymbolAddress((void**)&y,   g_y);
    cudaGetSymbolAddress((void**)&x1,  g_x1);
    cudaGetSymbolAddress((void**)&an,  g_Aneg);
    cudaGetSymbolAddress((void**)&fl,  g_flag);

    init_k<<<1, 32>>>();
    prep_k<<<(DEPTH*DINNER*DSTATE + 255) / 256, 256>>>(alog);

    for (int L = 0; L < DEPTH; L++) {
        const float* xin  = (L == 0) ? x : x1;
        float*       xout = (L == DEPTH - 1) ? (float*)d_out : x1;

        // 1. LayerNorm
        ln_k<<<NTOK / 8, 256>>>(xin, lnw + L*DMODEL, lnb + L*DMODEL, xn);

        // 2. in_proj: [16384,512] x [2048,512]^T -> xz
        mma_gemm<128, 0><<<dim3(2*DINNER/128, NTOK/128), 256>>>(
            xn, DMODEL, inw + (size_t)L*2*DINNER*DMODEL, nullptr, nullptr,
            xz, NTOK, 2*DINNER, DMODEL);

        // 3. depthwise conv + bias + silu -> xc (u)
        conv_k<<<(NTOK*DINNER) / 256, 256>>>(xz, cw + L*DINNER*4, cb + L*DINNER, xc);

        // 4. x_proj: [16384,1024] x [64,1024]^T -> dbc
        mma_gemm<64, 0><<<dim3(1, NTOK/128), 256>>>(
            xc, DINNER, xpw + (size_t)L*64*DINNER, nullptr, nullptr,
            dbc, NTOK, 64, DINNER);

        // 5. dt_proj + softplus: dbc[:, :32] (lda=64) x [1024,32]^T -> delta
        mma_gemm<128, 2><<<dim3(DINNER/128, NTOK/128), 256>>>(
            dbc, 64, dtw + (size_t)L*DINNER*DTRANK, dtb + L*DINNER, nullptr,
            del, NTOK, DINNER, DTRANK);

        // 6. selective scan + D-skip + silu(z) gate -> y
        scan_k<<<(BSZ*DINNER*4) / 128, 128>>>(del, xc, dbc, xz,
            an + L*DINNER*DSTATE, dpar + L*DINNER, fl + L, y);

        // 7. out_proj + residual: xout = xin + y x [512,1024]^T
        mma_gemm<128, 1><<<dim3(DMODEL/128, NTOK/128), 256>>>(
            y, DINNER, ow + (size_t)L*DMODEL*DINNER, nullptr, xin,
            xout, NTOK, DMODEL, DINNER);
    }
}

// round 12
// speedup vs baseline: 2.5437x; 1.4471x over previous
#include <cuda_runtime.h>
#include <cuda_bf16.h>
#include <cstdint>

#define DMODEL 512
#define DINNER 1024
#define DSTATE 16
#define DTRANK 32
#define BSZ 8
#define SEQ 2048
#define NTOK (BSZ*SEQ)      /* 16384 tokens */
#define DEPTH 2
#define NCH 8               /* scan chunks per sequence */
#define CHL (SEQ/NCH)       /* 256 timesteps per chunk */

// ---------------- scratch (device globals; no allocation allowed) ----------------
__device__ float g_xn[NTOK*DMODEL];                 // layernorm output
__device__ float g_xz[NTOK*2*DINNER];               // in_proj output (xi | z)
__device__ float g_xc[NTOK*DINNER];                 // conv+silu output (u)
__device__ float g_dbc[NTOK*64];                    // x_proj output (dt|B|C)
__device__ float g_delta[NTOK*DINNER];              // softplus(dt@dtw + dtb)
__device__ float g_y[NTOK*DINNER];                  // scan output (raw then gated)
__device__ float g_x1[NTOK*DMODEL];                 // residual stream after layer0
__device__ float g_Aneg[DEPTH*DINNER*DSTATE];       // A = -exp(A_log)
__device__ int   g_flag[DEPTH];                     // 0 => A[e][n]==(n+1)*A[e][0]
__device__ float g_hend[BSZ*NCH*DINNER*16];         // per-chunk local end states
__device__ float g_S[BSZ*NCH*DINNER];               // per-chunk sum of delta

// ---------------- small helpers ----------------
__device__ __forceinline__ float softplus_f(float v) {
    return (v > 20.f) ? v : log1pf(expf(v));
}
__device__ __forceinline__ float silu_f(float v) {
    return __fdividef(v, 1.f + __expf(-v));
}
__device__ __forceinline__ uint32_t smem_u32(const void* p) {
    uint32_t a;
    asm("{ .reg .u64 t; cvta.to.shared.u64 t, %1; cvt.u32.u64 %0, t; }" : "=r"(a) : "l"(p));
    return a;
}

// ldmatrix x4: lanes 0-7 -> matrix0 rows, 8-15 -> m1, 16-23 -> m2, 24-31 -> m3
#define LDSM4(R, addr)                                                        \
    asm volatile("ldmatrix.sync.aligned.m8n8.x4.shared.b16 {%0,%1,%2,%3}, [%4];" \
        : "=r"((R)[0]), "=r"((R)[1]), "=r"((R)[2]), "=r"((R)[3]) : "r"(addr))

#define MMA16816(Cc, Aa, B0, B1)                                              \
    asm volatile("mma.sync.aligned.m16n8k16.row.col.f32.bf16.bf16.f32 "       \
        "{%0,%1,%2,%3}, {%4,%5,%6,%7}, {%8,%9}, {%0,%1,%2,%3};"               \
        : "+f"((Cc)[0]), "+f"((Cc)[1]), "+f"((Cc)[2]), "+f"((Cc)[3])          \
        : "r"((Aa)[0]), "r"((Aa)[1]), "r"((Aa)[2]), "r"((Aa)[3]),             \
          "r"(B0), "r"(B1))

// split two fp32 into packed bf16 hi pair + lo (residual) pair
__device__ __forceinline__ void split2(float a, float b, uint32_t& h, uint32_t& l) {
    __nv_bfloat162 hb = __float22bfloat162_rn(make_float2(a, b));
    float ra = a - __bfloat162float(hb.x);
    float rb = b - __bfloat162float(hb.y);
    __nv_bfloat162 lb = __float22bfloat162_rn(make_float2(ra, rb));
    h = *(uint32_t*)&hb;
    l = *(uint32_t*)&lb;
}

// ---------------- init / precompute ----------------
__global__ void init_k() {
    if (threadIdx.x < DEPTH) g_flag[threadIdx.x] = 0;
}

__global__ void prep_k(const float* __restrict__ Alog) {
    int idx = blockIdx.x * blockDim.x + threadIdx.x;
    if (idx >= DEPTH * DINNER * DSTATE) return;
    float a = -expf(Alog[idx]);
    g_Aneg[idx] = a;
    int n = idx & 15;
    float a0 = -expf(Alog[idx & ~15]);
    if (fabsf(a - (float)(n + 1) * a0) > 1e-4f * fabsf(a) + 1e-12f)
        atomicOr(&g_flag[idx >> 14], 1);
}

// ---------------- LayerNorm: one warp per token ----------------
__global__ void __launch_bounds__(256)
ln_k(const float* __restrict__ x, const float* __restrict__ w,
     const float* __restrict__ b, float* __restrict__ o)
{
    int token = blockIdx.x * (blockDim.x >> 5) + (threadIdx.x >> 5);
    int lane = threadIdx.x & 31;
    const float4* xr = (const float4*)(x + (size_t)token * DMODEL);
    float4 v[4];
    float s = 0.f, sq = 0.f;
#pragma unroll
    for (int i = 0; i < 4; i++) {
        v[i] = xr[lane + 32 * i];
        s  += v[i].x + v[i].y + v[i].z + v[i].w;
        sq += v[i].x*v[i].x + v[i].y*v[i].y + v[i].z*v[i].z + v[i].w*v[i].w;
    }
#pragma unroll
    for (int off = 16; off; off >>= 1) {
        s  += __shfl_xor_sync(0xffffffffu, s,  off);
        sq += __shfl_xor_sync(0xffffffffu, sq, off);
    }
    float mu  = s * (1.f / DMODEL);
    float var = sq * (1.f / DMODEL) - mu * mu;
    float rs  = rsqrtf(var + 1e-5f);
    const float4* wr = (const float4*)w;
    const float4* br = (const float4*)b;
    float4* orow = (float4*)(o + (size_t)token * DMODEL);
#pragma unroll
    for (int i = 0; i < 4; i++) {
        float4 wv = wr[lane + 32 * i], bv = br[lane + 32 * i], xv = v[i], ov;
        ov.x = (xv.x - mu) * rs * wv.x + bv.x;
        ov.y = (xv.y - mu) * rs * wv.y + bv.y;
        ov.z = (xv.z - mu) * rs * wv.z + bv.z;
        ov.w = (xv.w - mu) * rs * wv.w + bv.w;
        orow[lane + 32 * i] = ov;
    }
}

// ---------------- depthwise causal conv(4) + bias + SiLU ----------------
__global__ void __launch_bounds__(256)
conv_k(const float* __restrict__ xz, const float* __restrict__ cw,
       const float* __restrict__ cb, float* __restrict__ xc)
{
    int idx = blockIdx.x * blockDim.x + threadIdx.x;
    int e = idx & (DINNER - 1);
    int t = idx >> 10;
    int l = t & (SEQ - 1);
    float4 w = ((const float4*)cw)[e];
    const float* base = xz + (size_t)t * (2 * DINNER) + e;
    float acc = cb[e] + w.w * base[0];
    if (l >= 1) acc += w.z * base[-(2 * DINNER)];
    if (l >= 2) acc += w.y * base[-2 * (2 * DINNER)];
    if (l >= 3) acc += w.x * base[-3 * (2 * DINNER)];
    xc[idx] = silu_f(acc);
}

// ---------------- bf16-split tensor-core GEMM via mma.sync ----------------
// C[M,N] = A[M,K] * B[N,K]^T (+epilogue). BM=128, BK=32, BN in {64,128}.
// 2-term bf16 split (hi+lo): 3 MMAs per fragment pair.
// EPI: 0 = none, 1 = +Res, 2 = softplus(acc + bias[n])
template<int BN, int EPI>
__global__ void __launch_bounds__(256, 1)
mma_gemm(const float* __restrict__ A, int lda,
         const float* __restrict__ B,
         const float* __restrict__ bias,
         const float* __restrict__ Res,
         float* __restrict__ C,
         int M, int N, int K)
{
    constexpr int RS = 40;                    // smem row stride (bf16): 80B, odd*16B -> conflict-free ldmatrix
    constexpr int WY = (BN == 128) ? 2 : 4;   // warps stacked along M
    constexpr int WM = 128 / WY;              // warp M tile
    constexpr int MF = WM / 16;               // A fragments per warp (4 or 2)
    constexpr int PB = BN / 32;               // per-thread B float4 loads per chunk

    __shared__ __align__(16) uint16_t sAh[128 * RS], sAl[128 * RS];
    __shared__ __align__(16) uint16_t sBh[BN  * RS], sBl[BN  * RS];

    const int tid = threadIdx.x, lane = tid & 31, wid = tid >> 5;
    const int wy = wid % WY, wx = wid / WY;
    const int mBase = blockIdx.y * 128, nBase = blockIdx.x * BN;

    float acc[MF][4][4];
#pragma unroll
    for (int i = 0; i < MF; i++)
#pragma unroll
        for (int j = 0; j < 4; j++)
#pragma unroll
            for (int t = 0; t < 4; t++) acc[i][j][t] = 0.f;

    // per-thread gmem load coordinates (fixed): row = lr + 32*i, col = lc..lc+3
    const int lr = tid >> 3;
    const int lc = (tid & 7) * 4;

    float4 pa[4], pb[PB];
#pragma unroll
    for (int i = 0; i < 4; i++)
        pa[i] = *(const float4*)(A + (size_t)(mBase + lr + 32 * i) * lda + lc);
#pragma unroll
    for (int i = 0; i < PB; i++)
        pb[i] = *(const float4*)(B + (size_t)(nBase + lr + 32 * i) * K + lc);

    const int nch = K >> 5;
    for (int c = 0; c < nch; c++) {
        if (c) __syncthreads();              // previous compute done before overwrite
        // convert + store current chunk
#pragma unroll
        for (int i = 0; i < 4; i++) {
            uint32_t h0, l0, h1, l1;
            split2(pa[i].x, pa[i].y, h0, l0);
            split2(pa[i].z, pa[i].w, h1, l1);
            int off = (lr + 32 * i) * RS + lc;
            *(uint2*)(sAh + off) = make_uint2(h0, h1);
            *(uint2*)(sAl + off) = make_uint2(l0, l1);
        }
#pragma unroll
        for (int i = 0; i < PB; i++) {
            uint32_t h0, l0, h1, l1;
            split2(pb[i].x, pb[i].y, h0, l0);
            split2(pb[i].z, pb[i].w, h1, l1);
            int off = (lr + 32 * i) * RS + lc;
            *(uint2*)(sBh + off) = make_uint2(h0, h1);
            *(uint2*)(sBl + off) = make_uint2(l0, l1);
        }
        __syncthreads();

        // prefetch next chunk into regs while MMAs run
        if (c + 1 < nch) {
            int k0 = (c + 1) << 5;
#pragma unroll 4
            for (int i = 0; i < 4; i++)
                pa[i] = *(const float4*)(A + (size_t)(mBase + lr + 32 * i) * lda + k0 + lc);
#pragma unroll
            for (int i = 0; i < PB; i++)
                pb[i] = *(const float4*)(B + (size_t)(nBase + lr + 32 * i) * K + k0 + lc);
        }

        const int q = lane >> 3, rr = lane & 7;
#pragma unroll
        for (int ks = 0; ks < 2; ks++) {
            uint32_t ah[MF][4], al[MF][4], bh[2][4], bl[2][4];
#pragma unroll
            for (int i = 0; i < MF; i++) {
                int row = wy * WM + i * 16 + (q & 1) * 8 + rr;
                int col = ks * 16 + (q >> 1) * 8;
                LDSM4(ah[i], smem_u32(sAh + row * RS + col));
                LDSM4(al[i], smem_u32(sAl + row * RS + col));
            }
#pragma unroll
            for (int p = 0; p < 2; p++) {
                int row = wx * 32 + p * 16 + (q >> 1) * 8 + rr;
                int col = ks * 16 + (q & 1) * 8;
                LDSM4(bh[p], smem_u32(sBh + row * RS + col));
                LDSM4(bl[p], smem_u32(sBl + row * RS + col));
            }
#pragma unroll
            for (int i = 0; i < MF; i++)
#pragma unroll
                for (int j = 0; j < 4; j++) {
                    const int p = j >> 1, s = (j & 1) * 2;
                    MMA16816(acc[i][j], ah[i], bh[p][s], bh[p][s + 1]);
                    MMA16816(acc[i][j], ah[i], bl[p][s], bl[p][s + 1]);
                    MMA16816(acc[i][j], al[i], bh[p][s], bh[p][s + 1]);
                }
        }
    }

    // ---------------- epilogue ----------------
#pragma unroll
    for (int i = 0; i < MF; i++) {
        int row0 = mBase + wy * WM + i * 16 + (lane >> 2);
#pragma unroll
        for (int j = 0; j < 4; j++) {
            int col = nBase + wx * 32 + j * 8 + (lane & 3) * 2;
#pragma unroll
            for (int hhalf = 0; hhalf < 2; hhalf++) {
                int row = row0 + hhalf * 8;
                float2 v = make_float2(acc[i][j][2 * hhalf], acc[i][j][2 * hhalf + 1]);
                if (EPI == 1) {
                    float2 r = *(const float2*)(Res + (size_t)row * N + col);
                    v.x += r.x; v.y += r.y;
                } else if (EPI == 2) {
                    float2 bb = *(const float2*)(bias + col);
                    v.x = softplus_f(v.x + bb.x);
                    v.y = softplus_f(v.y + bb.y);
                }
                *(float2*)(C + (size_t)row * N + col) = v;
            }
        }
    }
}

// ================= chunked selective scan =================
// exp(a*d_1)*exp(a*d_2)*... == exp(a*(d_1+d_2+...)) exactly, so chunk
// transitions compose in log space: 8 chunks of 256 run in parallel
// (pass 1: local scan), then pass 2 folds in the carried state via
// y_t += C_t . (exp(a*s_t) o h_in) and applies D-skip + gate.

// ---- pass 1: local chunk scan; emit raw y, end state, sum(delta) ----
template<bool STRUCT>
__device__ __forceinline__ void scan1_body(int b, int c, int e, int q,
    const float* __restrict__ delta, const float* __restrict__ u_,
    const float* __restrict__ dbc,   const float* __restrict__ Aneg,
    float* __restrict__ y)
{
    float a0v = Aneg[e * DSTATE + q * 4 + 0];
    float a1v = Aneg[e * DSTATE + q * 4 + 1];
    float a2v = Aneg[e * DSTATE + q * 4 + 2];
    float a3v = Aneg[e * DSTATE + q * 4 + 3];
    float a0  = Aneg[e * DSTATE];
    float h0 = 0.f, h1 = 0.f, h2 = 0.f, h3 = 0.f, s = 0.f;

    size_t tok0 = (size_t)b * SEQ + (size_t)c * CHL;
    const float* dp = delta + tok0 * DINNER + e;
    const float* up = u_    + tok0 * DINNER + e;
    const float4* bc = (const float4*)(dbc + tok0 * 64);
    float* yp = y + tok0 * DINNER + e;

    for (int l0 = 0; l0 < CHL; l0 += 4) {
        float db[4], ub[4]; float4 Bb[4], Cb[4];
#pragma unroll
        for (int j = 0; j < 4; j++) {
            int l = l0 + j;
            db[j] = __ldg(dp + (size_t)l * DINNER);
            ub[j] = __ldg(up + (size_t)l * DINNER);
            Bb[j] = __ldg(bc + l * 16 + 8  + q);
            Cb[j] = __ldg(bc + l * 16 + 12 + q);
        }
#pragma unroll
        for (int j = 0; j < 4; j++) {
            float d = db[j], uu = ub[j];
            float4 Bq = Bb[j], Cq = Cb[j];
            float dA0, dA1, dA2, dA3;
            if (STRUCT) {
                float p  = __expf(a0 * d);
                float p2 = p * p, p3 = p2 * p, p4 = p2 * p2;
                float p8 = p4 * p4;
                float p4q = 1.f;
                if (q & 1) p4q = p4;
                if (q & 2) p4q *= p8;
                dA0 = p4q * p; dA1 = p4q * p2; dA2 = p4q * p3; dA3 = p4q * p4;
            } else {
                dA0 = __expf(a0v * d); dA1 = __expf(a1v * d);
                dA2 = __expf(a2v * d); dA3 = __expf(a3v * d);
            }
            s += d;
            float du = d * uu;
            h0 = fmaf(dA0, h0, du * Bq.x);
            h1 = fmaf(dA1, h1, du * Bq.y);
            h2 = fmaf(dA2, h2, du * Bq.z);
            h3 = fmaf(dA3, h3, du * Bq.w);
            float r = fmaf(h0, Cq.x, fmaf(h1, Cq.y, fmaf(h2, Cq.z, h3 * Cq.w)));
            r += __shfl_xor_sync(0xffffffffu, r, 1);
            r += __shfl_xor_sync(0xffffffffu, r, 2);
            if (q == 0)
                yp[(size_t)(l0 + j) * DINNER] = r;   // raw (no skip/gate yet)
        }
    }
    int cid = (b * NCH + c) * DINNER + e;
    *(float4*)&g_hend[(size_t)cid * 16 + q * 4] = make_float4(h0, h1, h2, h3);
    if (q == 0) g_S[cid] = s;
}

__global__ void __launch_bounds__(128)
scan1_k(const float* __restrict__ delta, const float* __restrict__ u_,
        const float* __restrict__ dbc,   const float* __restrict__ Aneg,
        const int* __restrict__ flag,    float* __restrict__ y)
{
    int idx = blockIdx.x * 128 + threadIdx.x;
    int q = idx & 3;
    int chain = idx >> 2;
    int e = chain & (DINNER - 1);
    int t2 = chain >> 10;
    int c = t2 & (NCH - 1);
    int b = t2 >> 3;
    if (*flag == 0) scan1_body<true >(b, c, e, q, delta, u_, dbc, Aneg, y);
    else            scan1_body<false>(b, c, e, q, delta, u_, dbc, Aneg, y);
}

// ---- pass 2: fold carried state, apply D-skip + SiLU(z) gate ----
template<bool STRUCT>
__device__ __forceinline__ void scan2_body(int b, int c, int e, int q,
    const float* __restrict__ delta, const float* __restrict__ u_,
    const float* __restrict__ xz,    const float* __restrict__ dbc,
    const float* __restrict__ Aneg,  const float* __restrict__ Dp,
    float* __restrict__ y)
{
    float a0v = Aneg[e * DSTATE + q * 4 + 0];
    float a1v = Aneg[e * DSTATE + q * 4 + 1];
    float a2v = Aneg[e * DSTATE + q * 4 + 2];
    float a3v = Aneg[e * DSTATE + q * 4 + 3];
    float a0  = Aneg[e * DSTATE];
    float Dv = Dp[e];

    // combine preceding chunks: h_in = exp(a*S_cc)*h_in + h_end_cc
    float hin0 = 0.f, hin1 = 0.f, hin2 = 0.f, hin3 = 0.f;
    for (int cc = 0; cc < c; cc++) {
        int cid = (b * NCH + cc) * DINNER + e;
        float S = __ldg(&g_S[cid]);
        float4 he = *(const float4*)&g_hend[(size_t)cid * 16 + q * 4];
        float w0, w1, w2, w3;
        if (STRUCT) {
            float p  = __expf(a0 * S);
            float p2 = p * p, p3 = p2 * p, p4 = p2 * p2;
            float p8 = p4 * p4;
            float p4q = 1.f;
            if (q & 1) p4q = p4;
            if (q & 2) p4q *= p8;
            w0 = p4q * p; w1 = p4q * p2; w2 = p4q * p3; w3 = p4q * p4;
        } else {
            w0 = __expf(a0v * S); w1 = __expf(a1v * S);
            w2 = __expf(a2v * S); w3 = __expf(a3v * S);
        }
        hin0 = fmaf(w0, hin0, he.x);
        hin1 = fmaf(w1, hin1, he.y);
        hin2 = fmaf(w2, hin2, he.z);
        hin3 = fmaf(w3, hin3, he.w);
    }

    size_t tok0 = (size_t)b * SEQ + (size_t)c * CHL;
    const float* dp = delta + tok0 * DINNER + e;
    const float* up = u_    + tok0 * DINNER + e;
    const float* zp = xz    + tok0 * (2*DINNER) + DINNER + e;
    const float4* bc = (const float4*)(dbc + tok0 * 64);
    float* yp = y + tok0 * DINNER + e;

    const bool dead = (c == 0);   // no carried state; still must gate
    float s = 0.f;
    for (int l0 = 0; l0 < CHL; l0 += 4) {
        float db[4], ub[4], zb[4], yb[4]; float4 Cb[4];
#pragma unroll
        for (int j = 0; j < 4; j++) {
            int l = l0 + j;
            db[j] = __ldg(dp + (size_t)l * DINNER);
            ub[j] = __ldg(up + (size_t)l * DINNER);
            zb[j] = __ldg(zp + (size_t)l * (2*DINNER));
            yb[j] = yp[(size_t)l * DINNER];
            Cb[j] = __ldg(bc + l * 16 + 12 + q);
        }
#pragma unroll
        for (int j = 0; j < 4; j++) {
            s += db[j];
            float r = 0.f;
            if (!dead) {
                float4 Cq = Cb[j];
                float w0, w1, w2, w3;
                if (STRUCT) {
                    float p  = __expf(a0 * s);
                    float p2 = p * p, p3 = p2 * p, p4 = p2 * p2;
                    float p8 = p4 * p4;
                    float p4q = 1.f;
                    if (q & 1) p4q = p4;
                    if (q & 2) p4q *= p8;
                    w0 = p4q * p; w1 = p4q * p2; w2 = p4q * p3; w3 = p4q * p4;
                } else {
                    w0 = __expf(a0v * s); w1 = __expf(a1v * s);
                    w2 = __expf(a2v * s); w3 = __expf(a3v * s);
                }
                r = fmaf(w0 * hin0, Cq.x, fmaf(w1 * hin1, Cq.y,
                    fmaf(w2 * hin2, Cq.z, w3 * hin3 * Cq.w)));
                r += __shfl_xor_sync(0xffffffffu, r, 1);
                r += __shfl_xor_sync(0xffffffffu, r, 2);
            }
            if (q == 0)
                yp[(size_t)(l0 + j) * DINNER] =
                    (yb[j] + r + ub[j] * Dv) * silu_f(zb[j]);
        }
    }
}

__global__ void __launch_bounds__(128)
scan2_k(const float* __restrict__ delta, const float* __restrict__ u_,
        const float* __restrict__ xz,    const float* __restrict__ dbc,
        const float* __restrict__ Aneg,  const float* __restrict__ Dp,
        const int* __restrict__ flag,    float* __restrict__ y)
{
    int idx = blockIdx.x * 128 + threadIdx.x;
    int q = idx & 3;
    int chain = idx >> 2;
    int e = chain & (DINNER - 1);
    int t2 = chain >> 10;
    int c = t2 & (NCH - 1);
    int b = t2 >> 3;
    if (*flag == 0) scan2_body<true >(b, c, e, q, delta, u_, xz, dbc, Aneg, Dp, y);
    else            scan2_body<false>(b, c, e, q, delta, u_, xz, dbc, Aneg, Dp, y);
}

// ---------------- host launcher ----------------
extern "C" void kernel_launch(void* const* d_in, const int* in_sizes, int n_in,
                              void* d_out, int out_size)
{
    const float* x    = (const float*)d_in[0];
    const float* lnw  = (const float*)d_in[1];
    const float* lnb  = (const float*)d_in[2];
    const float* inw  = (const float*)d_in[3];
    const float* cw   = (const float*)d_in[4];
    const float* cb   = (const float*)d_in[5];
    const float* xpw  = (const float*)d_in[6];
    const float* dtw  = (const float*)d_in[7];
    const float* dtb  = (const float*)d_in[8];
    const float* alog = (const float*)d_in[9];
    const float* dpar = (const float*)d_in[10];
    const float* ow   = (const float*)d_in[11];

    float *xn, *xz, *xc, *dbc, *del, *y, *x1, *an; int* fl;
    cudaGetSymbolAddress((void**)&xn,  g_xn);
    cudaGetSymbolAddress((void**)&xz,  g_xz);
    cudaGetSymbolAddress((void**)&xc,  g_xc);
    cudaGetSymbolAddress((void**)&dbc, g_dbc);
    cudaGetSymbolAddress((void**)&del, g_delta);
    cudaGetSymbolAddress((void**)&y,   g_y);
    cudaGetSymbolAddress((void**)&x1,  g_x1);
    cudaGetSymbolAddress((void**)&an,  g_Aneg);
    cudaGetSymbolAddress((void**)&fl,  g_flag);

    init_k<<<1, 32>>>();
    prep_k<<<(DEPTH*DINNER*DSTATE + 255) / 256, 256>>>(alog);

    const int SCAN_BLK = (BSZ * NCH * DINNER * 4) / 128;   // 2048 blocks

    for (int L = 0; L < DEPTH; L++) {
        const float* xin  = (L == 0) ? x : x1;
        float*       xout = (L == DEPTH - 1) ? (float*)d_out : x1;

        // 1. LayerNorm
        ln_k<<<NTOK / 8, 256>>>(xin, lnw + L*DMODEL, lnb + L*DMODEL, xn);

        // 2. in_proj: [16384,512] x [2048,512]^T -> xz
        mma_gemm<128, 0><<<dim3(2*DINNER/128, NTOK/128), 256>>>(
            xn, DMODEL, inw + (size_t)L*2*DINNER*DMODEL, nullptr, nullptr,
            xz, NTOK, 2*DINNER, DMODEL);

        // 3. depthwise conv + bias + silu -> xc (u)
        conv_k<<<(NTOK*DINNER) / 256, 256>>>(xz, cw + L*DINNER*4, cb + L*DINNER, xc);

        // 4. x_proj: [16384,1024] x [64,1024]^T -> dbc
        mma_gemm<64, 0><<<dim3(1, NTOK/128), 256>>>(
            xc, DINNER, xpw + (size_t)L*64*DINNER, nullptr, nullptr,
            dbc, NTOK, 64, DINNER);

        // 5. dt_proj + softplus: dbc[:, :32] (lda=64) x [1024,32]^T -> delta
        mma_gemm<128, 2><<<dim3(DINNER/128, NTOK/128), 256>>>(
            dbc, 64, dtw + (size_t)L*DINNER*DTRANK, dtb + L*DINNER, nullptr,
            del, NTOK, DINNER, DTRANK);

        // 6. chunked selective scan (2 passes) + D-skip + silu(z) gate -> y
        scan1_k<<<SCAN_BLK, 128>>>(del, xc, dbc, an + L*DINNER*DSTATE, fl + L, y);
        scan2_k<<<SCAN_BLK, 128>>>(del, xc, xz, dbc, an + L*DINNER*DSTATE,
                                   dpar + L*DINNER, fl + L, y);

        // 7. out_proj + residual: xout = xin + y x [512,1024]^T
        mma_gemm<128, 1><<<dim3(DMODEL/128, NTOK/128), 256>>>(
            y, DINNER, ow + (size_t)L*DMODEL*DINNER, nullptr, xin,
            xout, NTOK, DMODEL, DINNER);
    }
}

// round 14
// speedup vs baseline: 2.7186x; 1.0688x over previous
#include <cuda_runtime.h>
#include <cuda_bf16.h>
#include <cstdint>

#define DMODEL 512
#define DINNER 1024
#define DSTATE 16
#define DTRANK 32
#define BSZ 8
#define SEQ 2048
#define NTOK (BSZ*SEQ)      /* 16384 tokens */
#define DEPTH 2
#define NCH 16              /* scan chunks per sequence */
#define CHL (SEQ/NCH)       /* 128 timesteps per chunk */

// ---------------- scratch (device globals; no allocation allowed) ----------------
__device__ float g_xz[NTOK*2*DINNER];               // in_proj output (xi | z)
__device__ float g_xc[NTOK*DINNER];                 // conv+silu output (u), fp32 for scan
__device__ float g_dbc[NTOK*64];                    // x_proj output fp32 (B, C for scan)
__device__ float g_delta[NTOK*DINNER];              // softplus(dt@dtw + dtb)
__device__ float g_y[NTOK*DINNER];                  // scan pass-1 raw output
__device__ float g_x1[NTOK*DMODEL];                 // residual stream after layer0
__device__ float g_Aneg[DEPTH*DINNER*DSTATE];       // A = -exp(A_log)
__device__ int   g_flag[DEPTH];                     // 0 => A[e][n]==(n+1)*A[e][0]
__device__ float g_hend[BSZ*NCH*DINNER*16];         // per-chunk local end states
__device__ float g_S[BSZ*NCH*DINNER];               // per-chunk sum of delta

// bf16 hi/lo planes (produced once; consumed by tensor-core GEMMs)
__device__ __align__(16) uint16_t g_xnh[NTOK*DMODEL],  g_xnl[NTOK*DMODEL];
__device__ __align__(16) uint16_t g_xch[NTOK*DINNER],  g_xcl[NTOK*DINNER];
__device__ __align__(16) uint16_t g_yh [NTOK*DINNER],  g_yl [NTOK*DINNER];
__device__ __align__(16) uint16_t g_dbch[NTOK*64],     g_dbcl[NTOK*64];
__device__ __align__(16) uint16_t g_inwh[DEPTH*2*DINNER*DMODEL], g_inwl[DEPTH*2*DINNER*DMODEL];
__device__ __align__(16) uint16_t g_owh [DEPTH*DMODEL*DINNER],   g_owl [DEPTH*DMODEL*DINNER];
__device__ __align__(16) uint16_t g_xpwh[DEPTH*64*DINNER],       g_xpwl[DEPTH*64*DINNER];
__device__ __align__(16) uint16_t g_dtwh[DEPTH*DINNER*DTRANK],   g_dtwl[DEPTH*DINNER*DTRANK];

// ---------------- small helpers ----------------
__device__ __forceinline__ float softplus_f(float v) {
    return (v > 20.f) ? v : log1pf(expf(v));
}
__device__ __forceinline__ float silu_f(float v) {
    return __fdividef(v, 1.f + __expf(-v));
}
__device__ __forceinline__ uint32_t smem_u32(const void* p) {
    uint32_t a;
    asm("{ .reg .u64 t; cvta.to.shared.u64 t, %1; cvt.u32.u64 %0, t; }" : "=r"(a) : "l"(p));
    return a;
}
// split two fp32 into packed bf16 hi pair + lo (residual) pair
__device__ __forceinline__ void split2(float a, float b, uint32_t& h, uint32_t& l) {
    __nv_bfloat162 hb = __float22bfloat162_rn(make_float2(a, b));
    float ra = a - __bfloat162float(hb.x);
    float rb = b - __bfloat162float(hb.y);
    __nv_bfloat162 lb = __float22bfloat162_rn(make_float2(ra, rb));
    h = *(uint32_t*)&hb;
    l = *(uint32_t*)&lb;
}
__device__ __forceinline__ void split1(float v, uint16_t& h, uint16_t& l) {
    __nv_bfloat16 hb = __float2bfloat16(v);
    h = __bfloat16_as_ushort(hb);
    l = __bfloat16_as_ushort(__float2bfloat16(v - __bfloat162float(hb)));
}

// ldmatrix x4
#define LDSM4(R, addr)                                                        \
    asm volatile("ldmatrix.sync.aligned.m8n8.x4.shared.b16 {%0,%1,%2,%3}, [%4];" \
        : "=r"((R)[0]), "=r"((R)[1]), "=r"((R)[2]), "=r"((R)[3]) : "r"(addr))

#define MMA16816(Cc, Aa, B0, B1)                                              \
    asm volatile("mma.sync.aligned.m16n8k16.row.col.f32.bf16.bf16.f32 "       \
        "{%0,%1,%2,%3}, {%4,%5,%6,%7}, {%8,%9}, {%0,%1,%2,%3};"               \
        : "+f"((Cc)[0]), "+f"((Cc)[1]), "+f"((Cc)[2]), "+f"((Cc)[3])          \
        : "r"((Aa)[0]), "r"((Aa)[1]), "r"((Aa)[2]), "r"((Aa)[3]),             \
          "r"(B0), "r"(B1))

// ---------------- init / precompute ----------------
__global__ void init_k() {
    if (threadIdx.x < DEPTH) g_flag[threadIdx.x] = 0;
}

__global__ void prep_k(const float* __restrict__ Alog) {
    int idx = blockIdx.x * blockDim.x + threadIdx.x;
    if (idx >= DEPTH * DINNER * DSTATE) return;
    float a = -expf(Alog[idx]);
    g_Aneg[idx] = a;
    int n = idx & 15;
    float a0 = -expf(Alog[idx & ~15]);
    if (fabsf(a - (float)(n + 1) * a0) > 1e-4f * fabsf(a) + 1e-12f)
        atomicOr(&g_flag[idx >> 14], 1);
}

// one-shot weight split fp32 -> bf16 hi/lo planes
__global__ void __launch_bounds__(256)
prepw_k(const float* __restrict__ W, uint16_t* __restrict__ H,
        uint16_t* __restrict__ L, int n)
{
    int i = blockIdx.x * blockDim.x + threadIdx.x;
    if (i < n) { uint16_t h, l; split1(W[i], h, l); H[i] = h; L[i] = l; }
}

// ---------------- LayerNorm: one warp per token; emits bf16 hi/lo planes ----------------
__global__ void __launch_bounds__(256)
ln_k(const float* __restrict__ x, const float* __restrict__ w,
     const float* __restrict__ b,
     uint16_t* __restrict__ oh, uint16_t* __restrict__ ol)
{
    int token = blockIdx.x * (blockDim.x >> 5) + (threadIdx.x >> 5);
    int lane = threadIdx.x & 31;
    const float4* xr = (const float4*)(x + (size_t)token * DMODEL);
    float4 v[4];
    float s = 0.f, sq = 0.f;
#pragma unroll
    for (int i = 0; i < 4; i++) {
        v[i] = xr[lane + 32 * i];
        s  += v[i].x + v[i].y + v[i].z + v[i].w;
        sq += v[i].x*v[i].x + v[i].y*v[i].y + v[i].z*v[i].z + v[i].w*v[i].w;
    }
#pragma unroll
    for (int off = 16; off; off >>= 1) {
        s  += __shfl_xor_sync(0xffffffffu, s,  off);
        sq += __shfl_xor_sync(0xffffffffu, sq, off);
    }
    float mu  = s * (1.f / DMODEL);
    float var = sq * (1.f / DMODEL) - mu * mu;
    float rs  = rsqrtf(var + 1e-5f);
    const float4* wr = (const float4*)w;
    const float4* br = (const float4*)b;
#pragma unroll
    for (int i = 0; i < 4; i++) {
        float4 wv = wr[lane + 32 * i], bv = br[lane + 32 * i], xv = v[i], ov;
        ov.x = (xv.x - mu) * rs * wv.x + bv.x;
        ov.y = (xv.y - mu) * rs * wv.y + bv.y;
        ov.z = (xv.z - mu) * rs * wv.z + bv.z;
        ov.w = (xv.w - mu) * rs * wv.w + bv.w;
        uint32_t h0, l0, h1, l1;
        split2(ov.x, ov.y, h0, l0);
        split2(ov.z, ov.w, h1, l1);
        size_t off = (size_t)token * DMODEL + lane * 4 + 128 * i;
        *(uint2*)(oh + off) = make_uint2(h0, h1);
        *(uint2*)(ol + off) = make_uint2(l0, l1);
    }
}

// ---------------- depthwise causal conv(4) + bias + SiLU; fp32 + planes ----------------
__global__ void __launch_bounds__(256)
conv_k(const float* __restrict__ xz, const float* __restrict__ cw,
       const float* __restrict__ cb, float* __restrict__ xc,
       uint16_t* __restrict__ xch, uint16_t* __restrict__ xcl)
{
    int idx = blockIdx.x * blockDim.x + threadIdx.x;
    int e = idx & (DINNER - 1);
    int t = idx >> 10;
    int l = t & (SEQ - 1);
    float4 w = ((const float4*)cw)[e];
    const float* base = xz + (size_t)t * (2 * DINNER) + e;
    float acc = cb[e] + w.w * base[0];
    if (l >= 1) acc += w.z * base[-(2 * DINNER)];
    if (l >= 2) acc += w.y * base[-2 * (2 * DINNER)];
    if (l >= 3) acc += w.x * base[-3 * (2 * DINNER)];
    float val = silu_f(acc);
    xc[idx] = val;
    uint16_t h, lo;
    split1(val, h, lo);
    xch[idx] = h; xcl[idx] = lo;
}

// ---------------- bf16-plane tensor-core GEMM via mma.sync ----------------
// C[M,N] = A[M,K] * B[N,K]^T with A,B pre-split into bf16 hi/lo planes.
// 3 MMAs per fragment pair (hi*hi + hi*lo + lo*hi). BM=128, BK=32, BN in {64,128}.
// EPI: 0 = none, 1 = +Res, 2 = softplus(acc + bias[n]) fp32, 3 = fp32 + hi/lo planes
template<int BN, int EPI>
__global__ void __launch_bounds__(256, 1)
mma_gemm_bf(const uint16_t* __restrict__ Ah, const uint16_t* __restrict__ Al, int lda,
            const uint16_t* __restrict__ Bh, const uint16_t* __restrict__ Bl, int ldb,
            const float* __restrict__ bias, const float* __restrict__ Res,
            float* __restrict__ C,
            uint16_t* __restrict__ Ch, uint16_t* __restrict__ Cl,
            int M, int N, int K)
{
    constexpr int RS = 40;                    // smem row stride (bf16): 80B -> conflict-free ldmatrix
    constexpr int WY = (BN == 128) ? 2 : 4;
    constexpr int WM = 128 / WY;
    constexpr int MF = WM / 16;
    constexpr int NB = BN / 64;               // B uint4-load iterations per thread

    __shared__ __align__(16) uint16_t sAh[128 * RS], sAl[128 * RS];
    __shared__ __align__(16) uint16_t sBh[BN  * RS], sBl[BN  * RS];

    const int tid = threadIdx.x, lane = tid & 31, wid = tid >> 5;
    const int wy = wid % WY, wx = wid / WY;
    const int mBase = blockIdx.y * 128, nBase = blockIdx.x * BN;

    float acc[MF][4][4];
#pragma unroll
    for (int i = 0; i < MF; i++)
#pragma unroll
        for (int j = 0; j < 4; j++)
#pragma unroll
            for (int t = 0; t < 4; t++) acc[i][j][t] = 0.f;

    // gmem prefetch registers: each uint4 = 8 bf16
    uint4 pah[2], pal[2], pbh[NB], pbl[NB];
#pragma unroll
    for (int it = 0; it < 2; it++) {
        int i = tid + it * 256, r = i >> 2, cl = (i & 3) * 8;
        pah[it] = *(const uint4*)(Ah + (size_t)(mBase + r) * lda + cl);
        pal[it] = *(const uint4*)(Al + (size_t)(mBase + r) * lda + cl);
    }
#pragma unroll
    for (int it = 0; it < NB; it++) {
        int i = tid + it * 256, r = i >> 2, cl = (i & 3) * 8;
        pbh[it] = *(const uint4*)(Bh + (size_t)(nBase + r) * ldb + cl);
        pbl[it] = *(const uint4*)(Bl + (size_t)(nBase + r) * ldb + cl);
    }

    const int nch = K >> 5;
    for (int c = 0; c < nch; c++) {
        if (c) __syncthreads();
        // store current chunk to smem
#pragma unroll
        for (int it = 0; it < 2; it++) {
            int i = tid + it * 256, r = i >> 2, cl = (i & 3) * 8;
            int off = r * RS + cl;
            *(uint4*)(sAh + off) = pah[it];
            *(uint4*)(sAl + off) = pal[it];
        }
#pragma unroll
        for (int it = 0; it < NB; it++) {
            int i = tid + it * 256, r = i >> 2, cl = (i & 3) * 8;
            int off = r * RS + cl;
            *(uint4*)(sBh + off) = pbh[it];
            *(uint4*)(sBl + off) = pbl[it];
        }
        __syncthreads();

        // prefetch next chunk while MMAs run
        if (c + 1 < nch) {
            int k0 = (c + 1) << 5;
#pragma unroll
            for (int it = 0; it < 2; it++) {
                int i = tid + it * 256, r = i >> 2, cl = (i & 3) * 8;
                pah[it] = *(const uint4*)(Ah + (size_t)(mBase + r) * lda + k0 + cl);
                pal[it] = *(const uint4*)(Al + (size_t)(mBase + r) * lda + k0 + cl);
            }
#pragma unroll
            for (int it = 0; it < NB; it++) {
                int i = tid + it * 256, r = i >> 2, cl = (i & 3) * 8;
                pbh[it] = *(const uint4*)(Bh + (size_t)(nBase + r) * ldb + k0 + cl);
                pbl[it] = *(const uint4*)(Bl + (size_t)(nBase + r) * ldb + k0 + cl);
            }
        }

        const int q = lane >> 3, rr = lane & 7;
#pragma unroll
        for (int ks = 0; ks < 2; ks++) {
            uint32_t ah[MF][4], al[MF][4], bh[2][4], bl[2][4];
#pragma unroll
            for (int i = 0; i < MF; i++) {
                int row = wy * WM + i * 16 + (q & 1) * 8 + rr;
                int col = ks * 16 + (q >> 1) * 8;
                LDSM4(ah[i], smem_u32(sAh + row * RS + col));
                LDSM4(al[i], smem_u32(sAl + row * RS + col));
            }
#pragma unroll
            for (int p = 0; p < 2; p++) {
                int row = wx * 32 + p * 16 + (q >> 1) * 8 + rr;
                int col = ks * 16 + (q & 1) * 8;
                LDSM4(bh[p], smem_u32(sBh + row * RS + col));
                LDSM4(bl[p], smem_u32(sBl + row * RS + col));
            }
#pragma unroll
            for (int i = 0; i < MF; i++)
#pragma unroll
                for (int j = 0; j < 4; j++) {
                    const int p = j >> 1, s = (j & 1) * 2;
                    MMA16816(acc[i][j], ah[i], bh[p][s], bh[p][s + 1]);
                    MMA16816(acc[i][j], ah[i], bl[p][s], bl[p][s + 1]);
                    MMA16816(acc[i][j], al[i], bh[p][s], bh[p][s + 1]);
                }
        }
    }

    // ---------------- epilogue ----------------
#pragma unroll
    for (int i = 0; i < MF; i++) {
        int row0 = mBase + wy * WM + i * 16 + (lane >> 2);
#pragma unroll
        for (int j = 0; j < 4; j++) {
            int col = nBase + wx * 32 + j * 8 + (lane & 3) * 2;
#pragma unroll
            for (int hhalf = 0; hhalf < 2; hhalf++) {
                int row = row0 + hhalf * 8;
                float2 v = make_float2(acc[i][j][2 * hhalf], acc[i][j][2 * hhalf + 1]);
                if (EPI == 1) {
                    float2 r = *(const float2*)(Res + (size_t)row * N + col);
                    v.x += r.x; v.y += r.y;
                } else if (EPI == 2) {
                    float2 bb = *(const float2*)(bias + col);
                    v.x = softplus_f(v.x + bb.x);
                    v.y = softplus_f(v.y + bb.y);
                }
                *(float2*)(C + (size_t)row * N + col) = v;
                if (EPI == 3) {
                    uint32_t hp, lp;
                    split2(v.x, v.y, hp, lp);
                    *(uint32_t*)(Ch + (size_t)row * N + col) = hp;
                    *(uint32_t*)(Cl + (size_t)row * N + col) = lp;
                }
            }
        }
    }
}

// ================= chunked selective scan (NCH chunks of CHL) =================
// exp(a*d_1)*...*exp(a*d_k) == exp(a*(d_1+...+d_k)) exactly.

// ---- pass 1: local chunk scan; emit raw y, end state, sum(delta) ----
template<bool STRUCT>
__device__ __forceinline__ void scan1_body(int b, int c, int e, int q,
    const float* __restrict__ delta, const float* __restrict__ u_,
    const float* __restrict__ dbc,   const float* __restrict__ Aneg,
    float* __restrict__ y)
{
    float a0v = Aneg[e * DSTATE + q * 4 + 0];
    float a1v = Aneg[e * DSTATE + q * 4 + 1];
    float a2v = Aneg[e * DSTATE + q * 4 + 2];
    float a3v = Aneg[e * DSTATE + q * 4 + 3];
    float a0  = Aneg[e * DSTATE];
    float h0 = 0.f, h1 = 0.f, h2 = 0.f, h3 = 0.f, s = 0.f;

    size_t tok0 = (size_t)b * SEQ + (size_t)c * CHL;
    const float* dp = delta + tok0 * DINNER + e;
    const float* up = u_    + tok0 * DINNER + e;
    const float4* bc = (const float4*)(dbc + tok0 * 64);
    float* yp = y + tok0 * DINNER + e;

    for (int l0 = 0; l0 < CHL; l0 += 4) {
        float db[4], ub[4]; float4 Bb[4], Cb[4];
#pragma unroll
        for (int j = 0; j < 4; j++) {
            int l = l0 + j;
            db[j] = __ldg(dp + (size_t)l * DINNER);
            ub[j] = __ldg(up + (size_t)l * DINNER);
            Bb[j] = __ldg(bc + l * 16 + 8  + q);
            Cb[j] = __ldg(bc + l * 16 + 12 + q);
        }
#pragma unroll
        for (int j = 0; j < 4; j++) {
            float d = db[j], uu = ub[j];
            float4 Bq = Bb[j], Cq = Cb[j];
            float dA0, dA1, dA2, dA3;
            if (STRUCT) {
                float p  = __expf(a0 * d);
                float p2 = p * p, p3 = p2 * p, p4 = p2 * p2;
                float p8 = p4 * p4;
                float p4q = 1.f;
                if (q & 1) p4q = p4;
                if (q & 2) p4q *= p8;
                dA0 = p4q * p; dA1 = p4q * p2; dA2 = p4q * p3; dA3 = p4q * p4;
            } else {
                dA0 = __expf(a0v * d); dA1 = __expf(a1v * d);
                dA2 = __expf(a2v * d); dA3 = __expf(a3v * d);
            }
            s += d;
            float du = d * uu;
            h0 = fmaf(dA0, h0, du * Bq.x);
            h1 = fmaf(dA1, h1, du * Bq.y);
            h2 = fmaf(dA2, h2, du * Bq.z);
            h3 = fmaf(dA3, h3, du * Bq.w);
            float r = fmaf(h0, Cq.x, fmaf(h1, Cq.y, fmaf(h2, Cq.z, h3 * Cq.w)));
            r += __shfl_xor_sync(0xffffffffu, r, 1);
            r += __shfl_xor_sync(0xffffffffu, r, 2);
            if (q == 0)
                yp[(size_t)(l0 + j) * DINNER] = r;   // raw (no skip/gate yet)
        }
    }
    int cid = (b * NCH + c) * DINNER + e;
    *(float4*)&g_hend[(size_t)cid * 16 + q * 4] = make_float4(h0, h1, h2, h3);
    if (q == 0) g_S[cid] = s;
}

__global__ void __launch_bounds__(128)
scan1_k(const float* __restrict__ delta, const float* __restrict__ u_,
        const float* __restrict__ dbc,   const float* __restrict__ Aneg,
        const int* __restrict__ flag,    float* __restrict__ y)
{
    int idx = blockIdx.x * 128 + threadIdx.x;
    int q = idx & 3;
    int chain = idx >> 2;
    int e = chain & (DINNER - 1);
    int t2 = chain >> 10;
    int c = t2 & (NCH - 1);
    int b = t2 / NCH;
    if (*flag == 0) scan1_body<true >(b, c, e, q, delta, u_, dbc, Aneg, y);
    else            scan1_body<false>(b, c, e, q, delta, u_, dbc, Aneg, y);
}

// ---- pass 2: fold carried state, apply D-skip + SiLU(z) gate; emit bf16 planes ----
template<bool STRUCT>
__device__ __forceinline__ void scan2_body(int b, int c, int e, int q,
    const float* __restrict__ delta, const float* __restrict__ u_,
    const float* __restrict__ xz,    const float* __restrict__ dbc,
    const float* __restrict__ Aneg,  const float* __restrict__ Dp,
    const float* __restrict__ y,
    uint16_t* __restrict__ yh, uint16_t* __restrict__ yl)
{
    float a0v = Aneg[e * DSTATE + q * 4 + 0];
    float a1v = Aneg[e * DSTATE + q * 4 + 1];
    float a2v = Aneg[e * DSTATE + q * 4 + 2];
    float a3v = Aneg[e * DSTATE + q * 4 + 3];
    float a0  = Aneg[e * DSTATE];
    float Dv = Dp[e];

    // combine preceding chunks: h_in = exp(a*S_cc)*h_in + h_end_cc
    float hin0 = 0.f, hin1 = 0.f, hin2 = 0.f, hin3 = 0.f;
    for (int cc = 0; cc < c; cc++) {
        int cid = (b * NCH + cc) * DINNER + e;
        float S = __ldg(&g_S[cid]);
        float4 he = *(const float4*)&g_hend[(size_t)cid * 16 + q * 4];
        float w0, w1, w2, w3;
        if (STRUCT) {
            float p  = __expf(a0 * S);
            float p2 = p * p, p3 = p2 * p, p4 = p2 * p2;
            float p8 = p4 * p4;
            float p4q = 1.f;
            if (q & 1) p4q = p4;
            if (q & 2) p4q *= p8;
            w0 = p4q * p; w1 = p4q * p2; w2 = p4q * p3; w3 = p4q * p4;
        } else {
            w0 = __expf(a0v * S); w1 = __expf(a1v * S);
            w2 = __expf(a2v * S); w3 = __expf(a3v * S);
        }
        hin0 = fmaf(w0, hin0, he.x);
        hin1 = fmaf(w1, hin1, he.y);
        hin2 = fmaf(w2, hin2, he.z);
        hin3 = fmaf(w3, hin3, he.w);
    }

    size_t tok0 = (size_t)b * SEQ + (size_t)c * CHL;
    const float* dp = delta + tok0 * DINNER + e;
    const float* up = u_    + tok0 * DINNER + e;
    const float* zp = xz    + tok0 * (2*DINNER) + DINNER + e;
    const float4* bc = (const float4*)(dbc + tok0 * 64);
    const float* yp = y + tok0 * DINNER + e;
    uint16_t* yhp = yh + tok0 * DINNER + e;
    uint16_t* ylp = yl + tok0 * DINNER + e;

    const bool dead = (c == 0);
    float s = 0.f;
    for (int l0 = 0; l0 < CHL; l0 += 4) {
        float db[4], ub[4], zb[4], yb[4]; float4 Cb[4];
#pragma unroll
        for (int j = 0; j < 4; j++) {
            int l = l0 + j;
            db[j] = __ldg(dp + (size_t)l * DINNER);
            ub[j] = __ldg(up + (size_t)l * DINNER);
            zb[j] = __ldg(zp + (size_t)l * (2*DINNER));
            yb[j] = __ldg(yp + (size_t)l * DINNER);
            Cb[j] = __ldg(bc + l * 16 + 12 + q);
        }
#pragma unroll
        for (int j = 0; j < 4; j++) {
            s += db[j];
            float r = 0.f;
            if (!dead) {
                float4 Cq = Cb[j];
                float w0, w1, w2, w3;
                if (STRUCT) {
                    float p  = __expf(a0 * s);
                    float p2 = p * p, p3 = p2 * p, p4 = p2 * p2;
                    float p8 = p4 * p4;
                    float p4q = 1.f;
                    if (q & 1) p4q = p4;
                    if (q & 2) p4q *= p8;
                    w0 = p4q * p; w1 = p4q * p2; w2 = p4q * p3; w3 = p4q * p4;
                } else {
                    w0 = __expf(a0v * s); w1 = __expf(a1v * s);
                    w2 = __expf(a2v * s); w3 = __expf(a3v * s);
                }
                r = fmaf(w0 * hin0, Cq.x, fmaf(w1 * hin1, Cq.y,
                    fmaf(w2 * hin2, Cq.z, w3 * hin3 * Cq.w)));
                r += __shfl_xor_sync(0xffffffffu, r, 1);
                r += __shfl_xor_sync(0xffffffffu, r, 2);
            }
            if (q == 0) {
                float val = (yb[j] + r + ub[j] * Dv) * silu_f(zb[j]);
                uint16_t h, lo;
                split1(val, h, lo);
                yhp[(size_t)(l0 + j) * DINNER] = h;
                ylp[(size_t)(l0 + j) * DINNER] = lo;
            }
        }
    }
}

__global__ void __launch_bounds__(128)
scan2_k(const float* __restrict__ delta, const float* __restrict__ u_,
        const float* __restrict__ xz,    const float* __restrict__ dbc,
        const float* __restrict__ Aneg,  const float* __restrict__ Dp,
        const int* __restrict__ flag,    const float* __restrict__ y,
        uint16_t* __restrict__ yh,       uint16_t* __restrict__ yl)
{
    int idx = blockIdx.x * 128 + threadIdx.x;
    int q = idx & 3;
    int chain = idx >> 2;
    int e = chain & (DINNER - 1);
    int t2 = chain >> 10;
    int c = t2 & (NCH - 1);
    int b = t2 / NCH;
    if (*flag == 0) scan2_body<true >(b, c, e, q, delta, u_, xz, dbc, Aneg, Dp, y, yh, yl);
    else            scan2_body<false>(b, c, e, q, delta, u_, xz, dbc, Aneg, Dp, y, yh, yl);
}

// ---------------- host launcher ----------------
extern "C" void kernel_launch(void* const* d_in, const int* in_sizes, int n_in,
                              void* d_out, int out_size)
{
    const float* x    = (const float*)d_in[0];
    const float* lnw  = (const float*)d_in[1];
    const float* lnb  = (const float*)d_in[2];
    const float* inw  = (const float*)d_in[3];
    const float* cw   = (const float*)d_in[4];
    const float* cb   = (const float*)d_in[5];
    const float* xpw  = (const float*)d_in[6];
    const float* dtw  = (const float*)d_in[7];
    const float* dtb  = (const float*)d_in[8];
    const float* alog = (const float*)d_in[9];
    const float* dpar = (const float*)d_in[10];
    const float* ow   = (const float*)d_in[11];

    float *xz, *xc, *dbc, *del, *y, *x1, *an; int* fl;
    uint16_t *xnh, *xnl, *xch, *xcl, *yh, *yl, *dbch, *dbcl;
    uint16_t *inwh, *inwl, *owh, *owl, *xpwh, *xpwl, *dtwh, *dtwl;
    cudaGetSymbolAddress((void**)&xz,  g_xz);
    cudaGetSymbolAddress((void**)&xc,  g_xc);
    cudaGetSymbolAddress((void**)&dbc, g_dbc);
    cudaGetSymbolAddress((void**)&del, g_delta);
    cudaGetSymbolAddress((void**)&y,   g_y);
    cudaGetSymbolAddress((void**)&x1,  g_x1);
    cudaGetSymbolAddress((void**)&an,  g_Aneg);
    cudaGetSymbolAddress((void**)&fl,  g_flag);
    cudaGetSymbolAddress((void**)&xnh, g_xnh);  cudaGetSymbolAddress((void**)&xnl, g_xnl);
    cudaGetSymbolAddress((void**)&xch, g_xch);  cudaGetSymbolAddress((void**)&xcl, g_xcl);
    cudaGetSymbolAddress((void**)&yh,  g_yh);   cudaGetSymbolAddress((void**)&yl,  g_yl);
    cudaGetSymbolAddress((void**)&dbch,g_dbch); cudaGetSymbolAddress((void**)&dbcl,g_dbcl);
    cudaGetSymbolAddress((void**)&inwh,g_inwh); cudaGetSymbolAddress((void**)&inwl,g_inwl);
    cudaGetSymbolAddress((void**)&owh, g_owh);  cudaGetSymbolAddress((void**)&owl, g_owl);
    cudaGetSymbolAddress((void**)&xpwh,g_xpwh); cudaGetSymbolAddress((void**)&xpwl,g_xpwl);
    cudaGetSymbolAddress((void**)&dtwh,g_dtwh); cudaGetSymbolAddress((void**)&dtwl,g_dtwl);

    init_k<<<1, 32>>>();
    prep_k<<<(DEPTH*DINNER*DSTATE + 255) / 256, 256>>>(alog);
    { int n = DEPTH*2*DINNER*DMODEL; prepw_k<<<(n+255)/256, 256>>>(inw, inwh, inwl, n); }
    { int n = DEPTH*DMODEL*DINNER;   prepw_k<<<(n+255)/256, 256>>>(ow,  owh,  owl,  n); }
    { int n = DEPTH*64*DINNER;       prepw_k<<<(n+255)/256, 256>>>(xpw, xpwh, xpwl, n); }
    { int n = DEPTH*DINNER*DTRANK;   prepw_k<<<(n+255)/256, 256>>>(dtw, dtwh, dtwl, n); }

    const int SCAN_BLK = (BSZ * NCH * DINNER * 4) / 128;

    for (int L = 0; L < DEPTH; L++) {
        const float* xin  = (L == 0) ? x : x1;
        float*       xout = (L == DEPTH - 1) ? (float*)d_out : x1;

        // 1. LayerNorm -> bf16 planes
        ln_k<<<NTOK / 8, 256>>>(xin, lnw + L*DMODEL, lnb + L*DMODEL, xnh, xnl);

        // 2. in_proj: [16384,512] x [2048,512]^T -> xz fp32
        mma_gemm_bf<128, 0><<<dim3(2*DINNER/128, NTOK/128), 256>>>(
            xnh, xnl, DMODEL,
            inwh + (size_t)L*2*DINNER*DMODEL, inwl + (size_t)L*2*DINNER*DMODEL, DMODEL,
            nullptr, nullptr, xz, nullptr, nullptr, NTOK, 2*DINNER, DMODEL);

        // 3. depthwise conv + bias + silu -> xc fp32 + planes
        conv_k<<<(NTOK*DINNER) / 256, 256>>>(xz, cw + L*DINNER*4, cb + L*DINNER,
                                             xc, xch, xcl);

        // 4. x_proj: [16384,1024] x [64,1024]^T -> dbc fp32 + planes
        mma_gemm_bf<64, 3><<<dim3(1, NTOK/128), 256>>>(
            xch, xcl, DINNER,
            xpwh + (size_t)L*64*DINNER, xpwl + (size_t)L*64*DINNER, DINNER,
            nullptr, nullptr, dbc, dbch, dbcl, NTOK, 64, DINNER);

        // 5. dt_proj + softplus: dbc planes[:, :32] (lda=64) x [1024,32]^T -> delta fp32
        mma_gemm_bf<128, 2><<<dim3(DINNER/128, NTOK/128), 256>>>(
            dbch, dbcl, 64,
            dtwh + (size_t)L*DINNER*DTRANK, dtwl + (size_t)L*DINNER*DTRANK, DTRANK,
            dtb + L*DINNER, nullptr, del, nullptr, nullptr, NTOK, DINNER, DTRANK);

        // 6. chunked selective scan (2 passes) + D-skip + silu(z) gate -> y planes
        scan1_k<<<SCAN_BLK, 128>>>(del, xc, dbc, an + L*DINNER*DSTATE, fl + L, y);
        scan2_k<<<SCAN_BLK, 128>>>(del, xc, xz, dbc, an + L*DINNER*DSTATE,
                                   dpar + L*DINNER, fl + L, y, yh, yl);

        // 7. out_proj + residual: xout = xin + y x [512,1024]^T
        mma_gemm_bf<128, 1><<<dim3(DMODEL/128, NTOK/128), 256>>>(
            yh, yl, DINNER,
            owh + (size_t)L*DMODEL*DINNER, owl + (size_t)L*DMODEL*DINNER, DINNER,
            nullptr, xin, xout, nullptr, nullptr, NTOK, DMODEL, DINNER);
    }
}

// round 15
// speedup vs baseline: 2.8939x; 1.0645x over previous
#include <cuda_runtime.h>
#include <cuda_bf16.h>
#include <cstdint>

#define DMODEL 512
#define DINNER 1024
#define DSTATE 16
#define DTRANK 32
#define BSZ 8
#define SEQ 2048
#define NTOK (BSZ*SEQ)      /* 16384 tokens */
#define DEPTH 2
#define NCH 16              /* scan chunks per sequence */
#define CHL (SEQ/NCH)       /* 128 timesteps per chunk */

// ---------------- scratch (device globals; no allocation allowed) ----------------
__device__ float g_xz[NTOK*2*DINNER];               // in_proj output (xi | z)
__device__ float g_xc[NTOK*DINNER];                 // conv+silu output (u), fp32 for scan
__device__ float g_dbc[NTOK*64];                    // x_proj output fp32 (B, C for scan)
__device__ float g_delta[NTOK*DINNER];              // softplus(dt@dtw + dtb)
__device__ float g_y[NTOK*DINNER];                  // scan pass-1 raw output
__device__ float g_x1[NTOK*DMODEL];                 // residual stream after layer0
__device__ float g_Aneg[DEPTH*DINNER*DSTATE];       // A = -exp(A_log)
__device__ int   g_flag[DEPTH];                     // 0 => A[e][n]==(n+1)*A[e][0]
__device__ float g_hend[BSZ*NCH*DINNER*16];         // per-chunk local end states
__device__ float g_S[BSZ*NCH*DINNER];               // per-chunk sum of delta

// bf16 hi/lo planes (produced once; consumed by tensor-core GEMMs)
__device__ __align__(16) uint16_t g_xnh[NTOK*DMODEL],  g_xnl[NTOK*DMODEL];
__device__ __align__(16) uint16_t g_xch[NTOK*DINNER],  g_xcl[NTOK*DINNER];
__device__ __align__(16) uint16_t g_yh [NTOK*DINNER],  g_yl [NTOK*DINNER];
__device__ __align__(16) uint16_t g_dbch[NTOK*64],     g_dbcl[NTOK*64];
__device__ __align__(16) uint16_t g_inwh[DEPTH*2*DINNER*DMODEL], g_inwl[DEPTH*2*DINNER*DMODEL];
__device__ __align__(16) uint16_t g_owh [DEPTH*DMODEL*DINNER],   g_owl [DEPTH*DMODEL*DINNER];
__device__ __align__(16) uint16_t g_xpwh[DEPTH*64*DINNER],       g_xpwl[DEPTH*64*DINNER];
__device__ __align__(16) uint16_t g_dtwh[DEPTH*DINNER*DTRANK],   g_dtwl[DEPTH*DINNER*DTRANK];

// ---------------- small helpers ----------------
__device__ __forceinline__ float softplus_f(float v) {
    return (v > 20.f) ? v : log1pf(expf(v));
}
__device__ __forceinline__ float silu_f(float v) {
    return __fdividef(v, 1.f + __expf(-v));
}
__device__ __forceinline__ uint32_t smem_u32(const void* p) {
    uint32_t a;
    asm("{ .reg .u64 t; cvta.to.shared.u64 t, %1; cvt.u32.u64 %0, t; }" : "=r"(a) : "l"(p));
    return a;
}
// split two fp32 into packed bf16 hi pair + lo (residual) pair
__device__ __forceinline__ void split2(float a, float b, uint32_t& h, uint32_t& l) {
    __nv_bfloat162 hb = __float22bfloat162_rn(make_float2(a, b));
    float ra = a - __bfloat162float(hb.x);
    float rb = b - __bfloat162float(hb.y);
    __nv_bfloat162 lb = __float22bfloat162_rn(make_float2(ra, rb));
    h = *(uint32_t*)&hb;
    l = *(uint32_t*)&lb;
}
__device__ __forceinline__ void split1(float v, uint16_t& h, uint16_t& l) {
    __nv_bfloat16 hb = __float2bfloat16(v);
    h = __bfloat16_as_ushort(hb);
    l = __bfloat16_as_ushort(__float2bfloat16(v - __bfloat162float(hb)));
}

// ldmatrix x4
#define LDSM4(R, addr)                                                        \
    asm volatile("ldmatrix.sync.aligned.m8n8.x4.shared.b16 {%0,%1,%2,%3}, [%4];" \
        : "=r"((R)[0]), "=r"((R)[1]), "=r"((R)[2]), "=r"((R)[3]) : "r"(addr))

#define MMA16816(Cc, Aa, B0, B1)                                              \
    asm volatile("mma.sync.aligned.m16n8k16.row.col.f32.bf16.bf16.f32 "       \
        "{%0,%1,%2,%3}, {%4,%5,%6,%7}, {%8,%9}, {%0,%1,%2,%3};"               \
        : "+f"((Cc)[0]), "+f"((Cc)[1]), "+f"((Cc)[2]), "+f"((Cc)[3])          \
        : "r"((Aa)[0]), "r"((Aa)[1]), "r"((Aa)[2]), "r"((Aa)[3]),             \
          "r"(B0), "r"(B1))

// ---------------- init / precompute ----------------
__global__ void init_k() {
    if (threadIdx.x < DEPTH) g_flag[threadIdx.x] = 0;
}

__global__ void prep_k(const float* __restrict__ Alog) {
    int idx = blockIdx.x * blockDim.x + threadIdx.x;
    if (idx >= DEPTH * DINNER * DSTATE) return;
    float a = -expf(Alog[idx]);
    g_Aneg[idx] = a;
    int n = idx & 15;
    float a0 = -expf(Alog[idx & ~15]);
    if (fabsf(a - (float)(n + 1) * a0) > 1e-4f * fabsf(a) + 1e-12f)
        atomicOr(&g_flag[idx >> 14], 1);
}

// one-shot weight split fp32 -> bf16 hi/lo planes
__global__ void __launch_bounds__(256)
prepw_k(const float* __restrict__ W, uint16_t* __restrict__ H,
        uint16_t* __restrict__ L, int n)
{
    int i = blockIdx.x * blockDim.x + threadIdx.x;
    if (i < n) { uint16_t h, l; split1(W[i], h, l); H[i] = h; L[i] = l; }
}

// ---------------- LayerNorm: one warp per token; emits bf16 hi/lo planes ----------------
__global__ void __launch_bounds__(256)
ln_k(const float* __restrict__ x, const float* __restrict__ w,
     const float* __restrict__ b,
     uint16_t* __restrict__ oh, uint16_t* __restrict__ ol)
{
    int token = blockIdx.x * (blockDim.x >> 5) + (threadIdx.x >> 5);
    int lane = threadIdx.x & 31;
    const float4* xr = (const float4*)(x + (size_t)token * DMODEL);
    float4 v[4];
    float s = 0.f, sq = 0.f;
#pragma unroll
    for (int i = 0; i < 4; i++) {
        v[i] = xr[lane + 32 * i];
        s  += v[i].x + v[i].y + v[i].z + v[i].w;
        sq += v[i].x*v[i].x + v[i].y*v[i].y + v[i].z*v[i].z + v[i].w*v[i].w;
    }
#pragma unroll
    for (int off = 16; off; off >>= 1) {
        s  += __shfl_xor_sync(0xffffffffu, s,  off);
        sq += __shfl_xor_sync(0xffffffffu, sq, off);
    }
    float mu  = s * (1.f / DMODEL);
    float var = sq * (1.f / DMODEL) - mu * mu;
    float rs  = rsqrtf(var + 1e-5f);
    const float4* wr = (const float4*)w;
    const float4* br = (const float4*)b;
#pragma unroll
    for (int i = 0; i < 4; i++) {
        float4 wv = wr[lane + 32 * i], bv = br[lane + 32 * i], xv = v[i], ov;
        ov.x = (xv.x - mu) * rs * wv.x + bv.x;
        ov.y = (xv.y - mu) * rs * wv.y + bv.y;
        ov.z = (xv.z - mu) * rs * wv.z + bv.z;
        ov.w = (xv.w - mu) * rs * wv.w + bv.w;
        uint32_t h0, l0, h1, l1;
        split2(ov.x, ov.y, h0, l0);
        split2(ov.z, ov.w, h1, l1);
        size_t off = (size_t)token * DMODEL + lane * 4 + 128 * i;
        *(uint2*)(oh + off) = make_uint2(h0, h1);
        *(uint2*)(ol + off) = make_uint2(l0, l1);
    }
}

// ---------------- depthwise causal conv(4) + bias + SiLU; fp32 + planes ----------------
__global__ void __launch_bounds__(256)
conv_k(const float* __restrict__ xz, const float* __restrict__ cw,
       const float* __restrict__ cb, float* __restrict__ xc,
       uint16_t* __restrict__ xch, uint16_t* __restrict__ xcl)
{
    int idx = blockIdx.x * blockDim.x + threadIdx.x;
    int e = idx & (DINNER - 1);
    int t = idx >> 10;
    int l = t & (SEQ - 1);
    float4 w = ((const float4*)cw)[e];
    const float* base = xz + (size_t)t * (2 * DINNER) + e;
    float acc = cb[e] + w.w * base[0];
    if (l >= 1) acc += w.z * base[-(2 * DINNER)];
    if (l >= 2) acc += w.y * base[-2 * (2 * DINNER)];
    if (l >= 3) acc += w.x * base[-3 * (2 * DINNER)];
    float val = silu_f(acc);
    xc[idx] = val;
    uint16_t h, lo;
    split1(val, h, lo);
    xch[idx] = h; xcl[idx] = lo;
}

// ---------------- bf16-plane tensor-core GEMM, double-buffered smem ----------------
// C[M,N] = A[M,K] * B[N,K]^T with A,B pre-split into bf16 hi/lo planes.
// 3 MMAs per fragment pair (hi*hi + hi*lo + lo*hi). BM=128, BK=32, BN in {64,128}.
// 2-stage smem pipeline: one __syncthreads per chunk; STS of chunk c+1 and LDG
// of chunk c+2 overlap the MMAs of chunk c.
// EPI: 0 = none, 1 = +Res, 2 = softplus(acc + bias[n]) fp32, 3 = fp32 + hi/lo planes
template<int BN, int EPI>
__global__ void __launch_bounds__(256, 1)
mma_gemm_bf(const uint16_t* __restrict__ Ah, const uint16_t* __restrict__ Al, int lda,
            const uint16_t* __restrict__ Bh, const uint16_t* __restrict__ Bl, int ldb,
            const float* __restrict__ bias, const float* __restrict__ Res,
            float* __restrict__ C,
            uint16_t* __restrict__ Ch, uint16_t* __restrict__ Cl,
            int M, int N, int K)
{
    constexpr int RS = 40;                    // smem row stride (bf16): 80B -> conflict-free ldmatrix
    constexpr int WY = (BN == 128) ? 2 : 4;
    constexpr int WM = 128 / WY;
    constexpr int MF = WM / 16;
    constexpr int NB = BN / 64;               // B uint4-load iterations per thread
    constexpr int SA = 128 * RS;              // one A plane (u16 elems)
    constexpr int SB = BN * RS;
    constexpr int STG = 2 * SA + 2 * SB;      // one stage: Ah|Al|Bh|Bl

    extern __shared__ __align__(16) uint16_t sm[];

    const int tid = threadIdx.x, lane = tid & 31, wid = tid >> 5;
    const int wy = wid % WY, wx = wid / WY;
    const int mBase = blockIdx.y * 128, nBase = blockIdx.x * BN;

    float acc[MF][4][4];
#pragma unroll
    for (int i = 0; i < MF; i++)
#pragma unroll
        for (int j = 0; j < 4; j++)
#pragma unroll
            for (int t = 0; t < 4; t++) acc[i][j][t] = 0.f;

    // per-thread load/store coordinates (fixed): each uint4 = 8 bf16
    const int arow[2] = { (tid) >> 2, (tid + 256) >> 2 };
    const int acol = (tid & 3) * 8;

    uint4 pah[2], pal[2], pbh[NB], pbl[NB];

    auto ldgA = [&](int k0) {
#pragma unroll
        for (int it = 0; it < 2; it++) {
            pah[it] = *(const uint4*)(Ah + (size_t)(mBase + arow[it]) * lda + k0 + acol);
            pal[it] = *(const uint4*)(Al + (size_t)(mBase + arow[it]) * lda + k0 + acol);
        }
    };
    auto ldgB = [&](int k0) {
#pragma unroll
        for (int it = 0; it < NB; it++) {
            int r = (tid + it * 256) >> 2;
            pbh[it] = *(const uint4*)(Bh + (size_t)(nBase + r) * ldb + k0 + acol);
            pbl[it] = *(const uint4*)(Bl + (size_t)(nBase + r) * ldb + k0 + acol);
        }
    };
    auto stsAll = [&](uint16_t* st) {
#pragma unroll
        for (int it = 0; it < 2; it++) {
            int off = arow[it] * RS + acol;
            *(uint4*)(st + off) = pah[it];
            *(uint4*)(st + SA + off) = pal[it];
        }
#pragma unroll
        for (int it = 0; it < NB; it++) {
            int r = (tid + it * 256) >> 2;
            int off = r * RS + acol;
            *(uint4*)(st + 2 * SA + off) = pbh[it];
            *(uint4*)(st + 2 * SA + SB + off) = pbl[it];
        }
    };

    const int nch = K >> 5;
    // prologue: fill stage 0 with chunk 0, prefetch chunk 1 into regs
    ldgA(0); ldgB(0);
    stsAll(sm);
    if (nch > 1) { ldgA(32); ldgB(32); }
    __syncthreads();

    for (int c = 0; c < nch; c++) {
        uint16_t* st = sm + (c & 1) * STG;
        // overlap: store chunk c+1 to other stage, prefetch chunk c+2
        if (c + 1 < nch) stsAll(sm + ((c + 1) & 1) * STG);
        if (c + 2 < nch) { ldgA((c + 2) << 5); ldgB((c + 2) << 5); }

        const int q = lane >> 3, rr = lane & 7;
#pragma unroll
        for (int ks = 0; ks < 2; ks++) {
            uint32_t ah[MF][4], al[MF][4], bh[2][4], bl[2][4];
#pragma unroll
            for (int i = 0; i < MF; i++) {
                int row = wy * WM + i * 16 + (q & 1) * 8 + rr;
                int col = ks * 16 + (q >> 1) * 8;
                LDSM4(ah[i], smem_u32(st + row * RS + col));
                LDSM4(al[i], smem_u32(st + SA + row * RS + col));
            }
#pragma unroll
            for (int p = 0; p < 2; p++) {
                int row = wx * 32 + p * 16 + (q >> 1) * 8 + rr;
                int col = ks * 16 + (q & 1) * 8;
                LDSM4(bh[p], smem_u32(st + 2 * SA + row * RS + col));
                LDSM4(bl[p], smem_u32(st + 2 * SA + SB + row * RS + col));
            }
#pragma unroll
            for (int i = 0; i < MF; i++)
#pragma unroll
                for (int j = 0; j < 4; j++) {
                    const int p = j >> 1, s = (j & 1) * 2;
                    MMA16816(acc[i][j], ah[i], bh[p][s], bh[p][s + 1]);
                    MMA16816(acc[i][j], ah[i], bl[p][s], bl[p][s + 1]);
                    MMA16816(acc[i][j], al[i], bh[p][s], bh[p][s + 1]);
                }
        }
        if (c + 1 < nch) __syncthreads();
    }

    // ---------------- epilogue ----------------
#pragma unroll
    for (int i = 0; i < MF; i++) {
        int row0 = mBase + wy * WM + i * 16 + (lane >> 2);
#pragma unroll
        for (int j = 0; j < 4; j++) {
            int col = nBase + wx * 32 + j * 8 + (lane & 3) * 2;
#pragma unroll
            for (int hhalf = 0; hhalf < 2; hhalf++) {
                int row = row0 + hhalf * 8;
                float2 v = make_float2(acc[i][j][2 * hhalf], acc[i][j][2 * hhalf + 1]);
                if (EPI == 1) {
                    float2 r = *(const float2*)(Res + (size_t)row * N + col);
                    v.x += r.x; v.y += r.y;
                } else if (EPI == 2) {
                    float2 bb = *(const float2*)(bias + col);
                    v.x = softplus_f(v.x + bb.x);
                    v.y = softplus_f(v.y + bb.y);
                }
                *(float2*)(C + (size_t)row * N + col) = v;
                if (EPI == 3) {
                    uint32_t hp, lp;
                    split2(v.x, v.y, hp, lp);
                    *(uint32_t*)(Ch + (size_t)row * N + col) = hp;
                    *(uint32_t*)(Cl + (size_t)row * N + col) = lp;
                }
            }
        }
    }
}

// ================= chunked selective scan (NCH chunks of CHL) =================
// exp(a*d_1)*...*exp(a*d_k) == exp(a*(d_1+...+d_k)) exactly.

// ---- pass 1: local chunk scan; emit raw y, end state, sum(delta) ----
template<bool STRUCT>
__device__ __forceinline__ void scan1_body(int b, int c, int e, int q,
    const float* __restrict__ delta, const float* __restrict__ u_,
    const float* __restrict__ dbc,   const float* __restrict__ Aneg,
    float* __restrict__ y)
{
    float a0v = Aneg[e * DSTATE + q * 4 + 0];
    float a1v = Aneg[e * DSTATE + q * 4 + 1];
    float a2v = Aneg[e * DSTATE + q * 4 + 2];
    float a3v = Aneg[e * DSTATE + q * 4 + 3];
    float a0  = Aneg[e * DSTATE];
    float h0 = 0.f, h1 = 0.f, h2 = 0.f, h3 = 0.f, s = 0.f;

    size_t tok0 = (size_t)b * SEQ + (size_t)c * CHL;
    const float* dp = delta + tok0 * DINNER + e;
    const float* up = u_    + tok0 * DINNER + e;
    const float4* bc = (const float4*)(dbc + tok0 * 64);
    float* yp = y + tok0 * DINNER + e;

    for (int l0 = 0; l0 < CHL; l0 += 4) {
        float db[4], ub[4]; float4 Bb[4], Cb[4];
#pragma unroll
        for (int j = 0; j < 4; j++) {
            int l = l0 + j;
            db[j] = __ldg(dp + (size_t)l * DINNER);
            ub[j] = __ldg(up + (size_t)l * DINNER);
            Bb[j] = __ldg(bc + l * 16 + 8  + q);
            Cb[j] = __ldg(bc + l * 16 + 12 + q);
        }
#pragma unroll
        for (int j = 0; j < 4; j++) {
            float d = db[j], uu = ub[j];
            float4 Bq = Bb[j], Cq = Cb[j];
            float dA0, dA1, dA2, dA3;
            if (STRUCT) {
                float p  = __expf(a0 * d);
                float p2 = p * p, p3 = p2 * p, p4 = p2 * p2;
                float p8 = p4 * p4;
                float p4q = 1.f;
                if (q & 1) p4q = p4;
                if (q & 2) p4q *= p8;
                dA0 = p4q * p; dA1 = p4q * p2; dA2 = p4q * p3; dA3 = p4q * p4;
            } else {
                dA0 = __expf(a0v * d); dA1 = __expf(a1v * d);
                dA2 = __expf(a2v * d); dA3 = __expf(a3v * d);
            }
            s += d;
            float du = d * uu;
            h0 = fmaf(dA0, h0, du * Bq.x);
            h1 = fmaf(dA1, h1, du * Bq.y);
            h2 = fmaf(dA2, h2, du * Bq.z);
            h3 = fmaf(dA3, h3, du * Bq.w);
            float r = fmaf(h0, Cq.x, fmaf(h1, Cq.y, fmaf(h2, Cq.z, h3 * Cq.w)));
            r += __shfl_xor_sync(0xffffffffu, r, 1);
            r += __shfl_xor_sync(0xffffffffu, r, 2);
            if (q == 0)
                yp[(size_t)(l0 + j) * DINNER] = r;   // raw (no skip/gate yet)
        }
    }
    int cid = (b * NCH + c) * DINNER + e;
    *(float4*)&g_hend[(size_t)cid * 16 + q * 4] = make_float4(h0, h1, h2, h3);
    if (q == 0) g_S[cid] = s;
}

__global__ void __launch_bounds__(128)
scan1_k(const float* __restrict__ delta, const float* __restrict__ u_,
        const float* __restrict__ dbc,   const float* __restrict__ Aneg,
        const int* __restrict__ flag,    float* __restrict__ y)
{
    int idx = blockIdx.x * 128 + threadIdx.x;
    int q = idx & 3;
    int chain = idx >> 2;
    int e = chain & (DINNER - 1);
    int t2 = chain >> 10;
    int c = t2 & (NCH - 1);
    int b = t2 / NCH;
    if (*flag == 0) scan1_body<true >(b, c, e, q, delta, u_, dbc, Aneg, y);
    else            scan1_body<false>(b, c, e, q, delta, u_, dbc, Aneg, y);
}

// ---- pass 2: fold carried state, apply D-skip + SiLU(z) gate; emit bf16 planes ----
template<bool STRUCT>
__device__ __forceinline__ void scan2_body(int b, int c, int e, int q,
    const float* __restrict__ delta, const float* __restrict__ u_,
    const float* __restrict__ xz,    const float* __restrict__ dbc,
    const float* __restrict__ Aneg,  const float* __restrict__ Dp,
    const float* __restrict__ y,
    uint16_t* __restrict__ yh, uint16_t* __restrict__ yl)
{
    float a0v = Aneg[e * DSTATE + q * 4 + 0];
    float a1v = Aneg[e * DSTATE + q * 4 + 1];
    float a2v = Aneg[e * DSTATE + q * 4 + 2];
    float a3v = Aneg[e * DSTATE + q * 4 + 3];
    float a0  = Aneg[e * DSTATE];
    float Dv = Dp[e];

    // combine preceding chunks: h_in = exp(a*S_cc)*h_in + h_end_cc
    float hin0 = 0.f, hin1 = 0.f, hin2 = 0.f, hin3 = 0.f;
    for (int cc = 0; cc < c; cc++) {
        int cid = (b * NCH + cc) * DINNER + e;
        float S = __ldg(&g_S[cid]);
        float4 he = *(const float4*)&g_hend[(size_t)cid * 16 + q * 4];
        float w0, w1, w2, w3;
        if (STRUCT) {
            float p  = __expf(a0 * S);
            float p2 = p * p, p3 = p2 * p, p4 = p2 * p2;
            float p8 = p4 * p4;
            float p4q = 1.f;
            if (q & 1) p4q = p4;
            if (q & 2) p4q *= p8;
            w0 = p4q * p; w1 = p4q * p2; w2 = p4q * p3; w3 = p4q * p4;
        } else {
            w0 = __expf(a0v * S); w1 = __expf(a1v * S);
            w2 = __expf(a2v * S); w3 = __expf(a3v * S);
        }
        hin0 = fmaf(w0, hin0, he.x);
        hin1 = fmaf(w1, hin1, he.y);
        hin2 = fmaf(w2, hin2, he.z);
        hin3 = fmaf(w3, hin3, he.w);
    }

    size_t tok0 = (size_t)b * SEQ + (size_t)c * CHL;
    const float* dp = delta + tok0 * DINNER + e;
    const float* up = u_    + tok0 * DINNER + e;
    const float* zp = xz    + tok0 * (2*DINNER) + DINNER + e;
    const float4* bc = (const float4*)(dbc + tok0 * 64);
    const float* yp = y + tok0 * DINNER + e;
    uint16_t* yhp = yh + tok0 * DINNER + e;
    uint16_t* ylp = yl + tok0 * DINNER + e;

    const bool dead = (c == 0);
    float s = 0.f;
    for (int l0 = 0; l0 < CHL; l0 += 4) {
        float db[4], ub[4], zb[4], yb[4]; float4 Cb[4];
#pragma unroll
        for (int j = 0; j < 4; j++) {
            int l = l0 + j;
            db[j] = __ldg(dp + (size_t)l * DINNER);
            ub[j] = __ldg(up + (size_t)l * DINNER);
            zb[j] = __ldg(zp + (size_t)l * (2*DINNER));
            yb[j] = __ldg(yp + (size_t)l * DINNER);
            Cb[j] = __ldg(bc + l * 16 + 12 + q);
        }
#pragma unroll
        for (int j = 0; j < 4; j++) {
            s += db[j];
            float r = 0.f;
            if (!dead) {
                float4 Cq = Cb[j];
                float w0, w1, w2, w3;
                if (STRUCT) {
                    float p  = __expf(a0 * s);
                    float p2 = p * p, p3 = p2 * p, p4 = p2 * p2;
                    float p8 = p4 * p4;
                    float p4q = 1.f;
                    if (q & 1) p4q = p4;
                    if (q & 2) p4q *= p8;
                    w0 = p4q * p; w1 = p4q * p2; w2 = p4q * p3; w3 = p4q * p4;
                } else {
                    w0 = __expf(a0v * s); w1 = __expf(a1v * s);
                    w2 = __expf(a2v * s); w3 = __expf(a3v * s);
                }
                r = fmaf(w0 * hin0, Cq.x, fmaf(w1 * hin1, Cq.y,
                    fmaf(w2 * hin2, Cq.z, w3 * hin3 * Cq.w)));
                r += __shfl_xor_sync(0xffffffffu, r, 1);
                r += __shfl_xor_sync(0xffffffffu, r, 2);
            }
            if (q == 0) {
                float val = (yb[j] + r + ub[j] * Dv) * silu_f(zb[j]);
                uint16_t h, lo;
                split1(val, h, lo);
                yhp[(size_t)(l0 + j) * DINNER] = h;
                ylp[(size_t)(l0 + j) * DINNER] = lo;
            }
        }
    }
}

__global__ void __launch_bounds__(128)
scan2_k(const float* __restrict__ delta, const float* __restrict__ u_,
        const float* __restrict__ xz,    const float* __restrict__ dbc,
        const float* __restrict__ Aneg,  const float* __restrict__ Dp,
        const int* __restrict__ flag,    const float* __restrict__ y,
        uint16_t* __restrict__ yh,       uint16_t* __restrict__ yl)
{
    int idx = blockIdx.x * 128 + threadIdx.x;
    int q = idx & 3;
    int chain = idx >> 2;
    int e = chain & (DINNER - 1);
    int t2 = chain >> 10;
    int c = t2 & (NCH - 1);
    int b = t2 / NCH;
    if (*flag == 0) scan2_body<true >(b, c, e, q, delta, u_, xz, dbc, Aneg, Dp, y, yh, yl);
    else            scan2_body<false>(b, c, e, q, delta, u_, xz, dbc, Aneg, Dp, y, yh, yl);
}

// ---------------- host launcher ----------------
extern "C" void kernel_launch(void* const* d_in, const int* in_sizes, int n_in,
                              void* d_out, int out_size)
{
    const float* x    = (const float*)d_in[0];
    const float* lnw  = (const float*)d_in[1];
    const float* lnb  = (const float*)d_in[2];
    const float* inw  = (const float*)d_in[3];
    const float* cw   = (const float*)d_in[4];
    const float* cb   = (const float*)d_in[5];
    const float* xpw  = (const float*)d_in[6];
    const float* dtw  = (const float*)d_in[7];
    const float* dtb  = (const float*)d_in[8];
    const float* alog = (const float*)d_in[9];
    const float* dpar = (const float*)d_in[10];
    const float* ow   = (const float*)d_in[11];

    float *xz, *xc, *dbc, *del, *y, *x1, *an; int* fl;
    uint16_t *xnh, *xnl, *xch, *xcl, *yh, *yl, *dbch, *dbcl;
    uint16_t *inwh, *inwl, *owh, *owl, *xpwh, *xpwl, *dtwh, *dtwl;
    cudaGetSymbolAddress((void**)&xz,  g_xz);
    cudaGetSymbolAddress((void**)&xc,  g_xc);
    cudaGetSymbolAddress((void**)&dbc, g_dbc);
    cudaGetSymbolAddress((void**)&del, g_delta);
    cudaGetSymbolAddress((void**)&y,   g_y);
    cudaGetSymbolAddress((void**)&x1,  g_x1);
    cudaGetSymbolAddress((void**)&an,  g_Aneg);
    cudaGetSymbolAddress((void**)&fl,  g_flag);
    cudaGetSymbolAddress((void**)&xnh, g_xnh);  cudaGetSymbolAddress((void**)&xnl, g_xnl);
    cudaGetSymbolAddress((void**)&xch, g_xch);  cudaGetSymbolAddress((void**)&xcl, g_xcl);
    cudaGetSymbolAddress((void**)&yh,  g_yh);   cudaGetSymbolAddress((void**)&yl,  g_yl);
    cudaGetSymbolAddress((void**)&dbch,g_dbch); cudaGetSymbolAddress((void**)&dbcl,g_dbcl);
    cudaGetSymbolAddress((void**)&inwh,g_inwh); cudaGetSymbolAddress((void**)&inwl,g_inwl);
    cudaGetSymbolAddress((void**)&owh, g_owh);  cudaGetSymbolAddress((void**)&owl, g_owl);
    cudaGetSymbolAddress((void**)&xpwh,g_xpwh); cudaGetSymbolAddress((void**)&xpwl,g_xpwl);
    cudaGetSymbolAddress((void**)&dtwh,g_dtwh); cudaGetSymbolAddress((void**)&dtwl,g_dtwl);

    // dynamic smem opt-in (config calls; capture-safe)
    constexpr int SM128 = 2 * (2 * 128 * 40 + 2 * 128 * 40) * 2;   // 81920 B
    constexpr int SM64  = 2 * (2 * 128 * 40 + 2 * 64  * 40) * 2;   // 61440 B
    cudaFuncSetAttribute(mma_gemm_bf<128, 0>, cudaFuncAttributeMaxDynamicSharedMemorySize, SM128);
    cudaFuncSetAttribute(mma_gemm_bf<128, 1>, cudaFuncAttributeMaxDynamicSharedMemorySize, SM128);
    cudaFuncSetAttribute(mma_gemm_bf<128, 2>, cudaFuncAttributeMaxDynamicSharedMemorySize, SM128);
    cudaFuncSetAttribute(mma_gemm_bf<64,  3>, cudaFuncAttributeMaxDynamicSharedMemorySize, SM64);

    init_k<<<1, 32>>>();
    prep_k<<<(DEPTH*DINNER*DSTATE + 255) / 256, 256>>>(alog);
    { int n = DEPTH*2*DINNER*DMODEL; prepw_k<<<(n+255)/256, 256>>>(inw, inwh, inwl, n); }
    { int n = DEPTH*DMODEL*DINNER;   prepw_k<<<(n+255)/256, 256>>>(ow,  owh,  owl,  n); }
    { int n = DEPTH*64*DINNER;       prepw_k<<<(n+255)/256, 256>>>(xpw, xpwh, xpwl, n); }
    { int n = DEPTH*DINNER*DTRANK;   prepw_k<<<(n+255)/256, 256>>>(dtw, dtwh, dtwl, n); }

    const int SCAN_BLK = (BSZ * NCH * DINNER * 4) / 128;

    for (int L = 0; L < DEPTH; L++) {
        const float* xin  = (L == 0) ? x : x1;
        float*       xout = (L == DEPTH - 1) ? (float*)d_out : x1;

        // 1. LayerNorm -> bf16 planes
        ln_k<<<NTOK / 8, 256>>>(xin, lnw + L*DMODEL, lnb + L*DMODEL, xnh, xnl);

        // 2. in_proj: [16384,512] x [2048,512]^T -> xz fp32
        mma_gemm_bf<128, 0><<<dim3(2*DINNER/128, NTOK/128), 256, SM128>>>(
            xnh, xnl, DMODEL,
            inwh + (size_t)L*2*DINNER*DMODEL, inwl + (size_t)L*2*DINNER*DMODEL, DMODEL,
            nullptr, nullptr, xz, nullptr, nullptr, NTOK, 2*DINNER, DMODEL);

        // 3. depthwise conv + bias + silu -> xc fp32 + planes
        conv_k<<<(NTOK*DINNER) / 256, 256>>>(xz, cw + L*DINNER*4, cb + L*DINNER,
                                             xc, xch, xcl);

        // 4. x_proj: [16384,1024] x [64,1024]^T -> dbc fp32 + planes
        mma_gemm_bf<64, 3><<<dim3(1, NTOK/128), 256, SM64>>>(
            xch, xcl, DINNER,
            xpwh + (size_t)L*64*DINNER, xpwl + (size_t)L*64*DINNER, DINNER,
            nullptr, nullptr, dbc, dbch, dbcl, NTOK, 64, DINNER);

        // 5. dt_proj + softplus: dbc planes[:, :32] (lda=64) x [1024,32]^T -> delta fp32
        mma_gemm_bf<128, 2><<<dim3(DINNER/128, NTOK/128), 256, SM128>>>(
            dbch, dbcl, 64,
            dtwh + (size_t)L*DINNER*DTRANK, dtwl + (size_t)L*DINNER*DTRANK, DTRANK,
            dtb + L*DINNER, nullptr, del, nullptr, nullptr, NTOK, DINNER, DTRANK);

        // 6. chunked selective scan (2 passes) + D-skip + silu(z) gate -> y planes
        scan1_k<<<SCAN_BLK, 128>>>(del, xc, dbc, an + L*DINNER*DSTATE, fl + L, y);
        scan2_k<<<SCAN_BLK, 128>>>(del, xc, xz, dbc, an + L*DINNER*DSTATE,
                                   dpar + L*DINNER, fl + L, y, yh, yl);

        // 7. out_proj + residual: xout = xin + y x [512,1024]^T
        mma_gemm_bf<128, 1><<<dim3(DMODEL/128, NTOK/128), 256, SM128>>>(
            yh, yl, DINNER,
            owh + (size_t)L*DMODEL*DINNER, owl + (size_t)L*DMODEL*DINNER, DINNER,
            nullptr, xin, xout, nullptr, nullptr, NTOK, DMODEL, DINNER);
    }
}